// round 1
// baseline (speedup 1.0000x reference)
#include <cuda_runtime.h>
#include <math_constants.h>

// Problem constants
#define BB   8
#define NN   1024
#define FIN  256
#define OUTD 256
#define DD   4
#define MTOT (BB * NN)   // 8192

// ---------------- scratch (static device globals; no dynamic alloc) ----------------
__device__ float g_Wsum[DD * FIN * OUTD];                       // 1 MB
__device__ float g_wsrc[DD * FIN];
__device__ float g_wdst[DD * FIN];
__device__ float g_esrc[DD * MTOT];
__device__ float g_edst[DD * MTOT];
__device__ float g_Whsum[(size_t)DD * MTOT * OUTD];             // 33.5 MB
__device__ float g_alpha[(size_t)MTOT * NN];                    // 32 MB
__device__ __align__(16) unsigned char g_Apack[NN * NN];        // 1 MB

__device__ __forceinline__ float warpSum(float v) {
    #pragma unroll
    for (int o = 16; o; o >>= 1) v += __shfl_xor_sync(0xffffffffu, v, o);
    return v;
}

// ---------------- prep: W_sum = W[d,0]+W[d,1]; w_src/w_dst = W[d,1] @ a[d,1] ----------------
// grid: 1024 blocks = (d, f); 256 threads = o
__global__ void prep_kernel(const float* __restrict__ W, const float* __restrict__ a) {
    int d = blockIdx.x >> 8;
    int f = blockIdx.x & 255;
    int o = threadIdx.x;

    float w0 = W[((size_t)(d * 2 + 0) * FIN + f) * OUTD + o];
    float w1 = W[((size_t)(d * 2 + 1) * FIN + f) * OUTD + o];
    g_Wsum[(d * FIN + f) * OUTD + o] = w0 + w1;

    float a_s = a[(d * 2 + 1) * (2 * OUTD) + o];
    float a_d = a[(d * 2 + 1) * (2 * OUTD) + OUTD + o];
    float s1 = w1 * a_s;
    float s2 = w1 * a_d;

    s1 = warpSum(s1);
    s2 = warpSum(s2);
    __shared__ float r1[8], r2[8];
    int lane = threadIdx.x & 31, wid = threadIdx.x >> 5;
    if (lane == 0) { r1[wid] = s1; r2[wid] = s2; }
    __syncthreads();
    if (threadIdx.x == 0) {
        float t1 = 0.f, t2 = 0.f;
        #pragma unroll
        for (int w = 0; w < 8; w++) { t1 += r1[w]; t2 += r2[w]; }
        g_wsrc[d * FIN + f] = t1;
        g_wdst[d * FIN + f] = t2;
    }
}

// ---------------- pack adjacency bits: bit d set iff A_d[i,j] != 0 ----------------
__global__ void apack_kernel(const int* __restrict__ AU, const int* __restrict__ AD,
                             const int* __restrict__ AR, const int* __restrict__ AL) {
    int idx = blockIdx.x * 256 + threadIdx.x;   // 4096 * 256 = 1M
    unsigned m = (AU[idx] != 0 ? 1u : 0u) | (AD[idx] != 0 ? 2u : 0u) |
                 (AR[idx] != 0 ? 4u : 0u) | (AL[idx] != 0 ? 8u : 0u);
    g_Apack[idx] = (unsigned char)m;
}

// ---------------- projection GEMM: Whsum[d, m, o] = sum_f x[m,f] * Wsum[d,f,o] ----------------
// grid: (OUTD/64, MTOT/64, DD), 256 threads, 64x64 tile, 4x4 per thread
__global__ void proj_gemm(const float* __restrict__ x) {
    int d  = blockIdx.z;
    int m0 = blockIdx.y * 64;
    int o0 = blockIdx.x * 64;
    __shared__ __align__(16) float sX[64][33];
    __shared__ __align__(16) float sW[32][68];

    int t  = threadIdx.x;
    int tx = t & 15, ty = t >> 4;
    float acc[4][4];
    #pragma unroll
    for (int i = 0; i < 4; i++)
        #pragma unroll
        for (int j = 0; j < 4; j++) acc[i][j] = 0.f;

    for (int k0 = 0; k0 < FIN; k0 += 32) {
        #pragma unroll
        for (int s = 0; s < 8; s++) {
            int idx = t + 256 * s;
            int r = idx >> 5, c = idx & 31;
            sX[r][c] = x[(size_t)(m0 + r) * FIN + k0 + c];
        }
        #pragma unroll
        for (int s = 0; s < 8; s++) {
            int idx = t + 256 * s;
            int k = idx >> 6, c = idx & 63;
            sW[k][c] = g_Wsum[(d * FIN + k0 + k) * OUTD + o0 + c];
        }
        __syncthreads();
        #pragma unroll
        for (int k = 0; k < 32; k++) {
            float4 wv = *(const float4*)&sW[k][tx * 4];
            float p[4];
            #pragma unroll
            for (int ii = 0; ii < 4; ii++) p[ii] = sX[ty * 4 + ii][k];
            #pragma unroll
            for (int ii = 0; ii < 4; ii++) {
                acc[ii][0] += p[ii] * wv.x;
                acc[ii][1] += p[ii] * wv.y;
                acc[ii][2] += p[ii] * wv.z;
                acc[ii][3] += p[ii] * wv.w;
            }
        }
        __syncthreads();
    }
    #pragma unroll
    for (int ii = 0; ii < 4; ii++) {
        float4 v = make_float4(acc[ii][0], acc[ii][1], acc[ii][2], acc[ii][3]);
        *(float4*)&g_Whsum[((size_t)d * MTOT + m0 + ty * 4 + ii) * OUTD + o0 + tx * 4] = v;
    }
}

// ---------------- e_src/e_dst: one warp per (d, m) dot-product of length 256 ----------------
// grid: 4096 blocks x 256 threads = 32768 warps = DD * MTOT
__global__ void edge_kernel(const float* __restrict__ x) {
    int w    = (blockIdx.x * blockDim.x + threadIdx.x) >> 5;
    int lane = threadIdx.x & 31;
    int d = w >> 13;        // / 8192
    int m = w & 8191;
    const float* xr = x + (size_t)m * FIN;
    float s1 = 0.f, s2 = 0.f;
    #pragma unroll
    for (int it = 0; it < 8; it++) {
        int k = lane + 32 * it;
        float xv = xr[k];
        s1 += xv * g_wsrc[d * FIN + k];
        s2 += xv * g_wdst[d * FIN + k];
    }
    s1 = warpSum(s1);
    s2 = warpSum(s2);
    if (lane == 0) { g_esrc[w] = s1; g_edst[w] = s2; }
}

// ---------------- softmax over j for each (b, i) row ----------------
// grid: 8192 blocks (b*1024+i), 256 threads, 4 j per thread
__global__ void softmax_kernel() {
    int bid = blockIdx.x;
    int b = bid >> 10;
    int i = bid & 1023;
    int t = threadIdx.x;
    int lane = t & 31, wid = t >> 5;

    __shared__ float s_esrc[4];
    __shared__ float sred[8];
    __shared__ float sbcast;

    if (t < 4) s_esrc[t] = g_esrc[t * MTOT + bid];
    __syncthreads();

    const float NEGINF = -CUDART_INF_F;
    float ev[4];
    float lmax = NEGINF;
    #pragma unroll
    for (int s = 0; s < 4; s++) {
        int j = t + 256 * s;
        unsigned m = g_Apack[i * NN + j];
        float e = NEGINF;
        if (m) {
            int ds = 31 - __clz(m);
            float v = s_esrc[ds] + g_edst[ds * MTOT + b * NN + j];
            e = v > 0.f ? v : 0.01f * v;
        }
        ev[s] = e;
        lmax = fmaxf(lmax, e);
    }
    #pragma unroll
    for (int o = 16; o; o >>= 1) lmax = fmaxf(lmax, __shfl_xor_sync(0xffffffffu, lmax, o));
    if (lane == 0) sred[wid] = lmax;
    __syncthreads();
    if (t == 0) {
        float v = sred[0];
        #pragma unroll
        for (int w = 1; w < 8; w++) v = fmaxf(v, sred[w]);
        sbcast = v;
    }
    __syncthreads();
    float rmax = sbcast;
    __syncthreads();

    float ex[4];
    float lsum = 0.f;
    #pragma unroll
    for (int s = 0; s < 4; s++) {
        float e = ev[s];
        float x = (e == NEGINF) ? 0.f : __expf(e - rmax);
        ex[s] = x;
        lsum += x;
    }
    lsum = warpSum(lsum);
    if (lane == 0) sred[wid] = lsum;
    __syncthreads();
    if (t == 0) {
        float v = 0.f;
        #pragma unroll
        for (int w = 0; w < 8; w++) v += sred[w];
        sbcast = 1.f / v;
    }
    __syncthreads();
    float inv = sbcast;
    #pragma unroll
    for (int s = 0; s < 4; s++)
        g_alpha[(size_t)bid * NN + t + 256 * s] = ex[s] * inv;
}

// ---------------- output GEMM: out[b,i,o] = 0.5 * sum_d sum_j (alpha*maskbit_d) * Whsum[d,b,j,o] ----------------
// grid: (OUTD/64, NN/64, BB), 256 threads, 64x64 tile, 4x4 per thread, K = 4*1024
__global__ void out_gemm(float* __restrict__ out) {
    int b  = blockIdx.z;
    int i0 = blockIdx.y * 64;
    int o0 = blockIdx.x * 64;
    __shared__ __align__(16) float sAlpha[64][33];
    __shared__ __align__(8)  unsigned char sMask[64][32];
    __shared__ __align__(16) float sP[64][33];
    __shared__ __align__(16) float sW[32][68];

    int t  = threadIdx.x;
    int tx = t & 15, ty = t >> 4;
    float acc[4][4];
    #pragma unroll
    for (int i = 0; i < 4; i++)
        #pragma unroll
        for (int j = 0; j < 4; j++) acc[i][j] = 0.f;

    for (int j0 = 0; j0 < NN; j0 += 32) {
        #pragma unroll
        for (int s = 0; s < 8; s++) {
            int idx = t + 256 * s;
            int r = idx >> 5, c = idx & 31;
            sAlpha[r][c] = g_alpha[(size_t)(b * NN + i0 + r) * NN + j0 + c];
        }
        {
            int r = t >> 2, c8 = (t & 3) * 8;
            *(unsigned long long*)&sMask[r][c8] =
                *(const unsigned long long*)&g_Apack[(i0 + r) * NN + j0 + c8];
        }
        __syncthreads();

        for (int d = 0; d < DD; d++) {
            #pragma unroll
            for (int s = 0; s < 8; s++) {
                int idx = t + 256 * s;
                int k = idx >> 6, c = idx & 63;
                sW[k][c] = g_Whsum[((size_t)d * MTOT + b * NN + j0 + k) * OUTD + o0 + c];
            }
            #pragma unroll
            for (int s = 0; s < 8; s++) {
                int idx = t + 256 * s;
                int r = idx >> 5, c = idx & 31;
                sP[r][c] = ((sMask[r][c] >> d) & 1) ? sAlpha[r][c] : 0.f;
            }
            __syncthreads();
            #pragma unroll
            for (int k = 0; k < 32; k++) {
                float4 wv = *(const float4*)&sW[k][tx * 4];
                float p[4];
                #pragma unroll
                for (int ii = 0; ii < 4; ii++) p[ii] = sP[ty * 4 + ii][k];
                #pragma unroll
                for (int ii = 0; ii < 4; ii++) {
                    acc[ii][0] += p[ii] * wv.x;
                    acc[ii][1] += p[ii] * wv.y;
                    acc[ii][2] += p[ii] * wv.z;
                    acc[ii][3] += p[ii] * wv.w;
                }
            }
            __syncthreads();
        }
    }
    #pragma unroll
    for (int ii = 0; ii < 4; ii++) {
        float4 v = make_float4(acc[ii][0] * 0.5f, acc[ii][1] * 0.5f,
                               acc[ii][2] * 0.5f, acc[ii][3] * 0.5f);
        *(float4*)&out[(size_t)(b * NN + i0 + ty * 4 + ii) * OUTD + o0 + tx * 4] = v;
    }
}

// ---------------- launch ----------------
extern "C" void kernel_launch(void* const* d_in, const int* in_sizes, int n_in,
                              void* d_out, int out_size) {
    const float* x  = (const float*)d_in[0];
    const int*   AU = (const int*)d_in[1];
    const int*   AD = (const int*)d_in[2];
    const int*   AR = (const int*)d_in[3];
    const int*   AL = (const int*)d_in[4];
    const float* W  = (const float*)d_in[5];
    const float* a  = (const float*)d_in[6];
    float* out = (float*)d_out;

    prep_kernel<<<DD * FIN, 256>>>(W, a);
    apack_kernel<<<(NN * NN) / 256, 256>>>(AU, AD, AR, AL);
    proj_gemm<<<dim3(OUTD / 64, MTOT / 64, DD), 256>>>(x);
    edge_kernel<<<(DD * MTOT) / 8, 256>>>(x);
    softmax_kernel<<<MTOT, 256>>>();
    out_gemm<<<dim3(OUTD / 64, NN / 64, BB), 256>>>(out);
}

// round 6
// speedup vs baseline: 2.3414x; 2.3414x over previous
#include <cuda_runtime.h>
#include <cuda_bf16.h>
#include <math_constants.h>
#include <cstdint>

// Problem constants
#define BB   8
#define NN   1024
#define FIN  256
#define OUTD 256
#define DD   4
#define MTOT (BB * NN)   // 8192

// ---------------- scratch (static device globals; no dynamic alloc) ----------------
__device__ float g_wsrc[DD * FIN];
__device__ float g_wdst[DD * FIN];
__device__ float g_esrc[DD * MTOT];
__device__ float g_edst[DD * MTOT];
__device__ __align__(16) unsigned char g_Apack[NN * NN];                    // 1 MB
__device__ __align__(16) __nv_bfloat16 g_alpha_h[(size_t)MTOT * NN];        // 16 MB
__device__ __align__(16) __nv_bfloat16 g_alpha_l[(size_t)MTOT * NN];        // 16 MB
__device__ __align__(16) __nv_bfloat16 g_xt_h[BB * FIN * NN];               // 4 MB  [b][f][j]
__device__ __align__(16) __nv_bfloat16 g_xt_l[BB * FIN * NN];               // 4 MB
__device__ __align__(16) __nv_bfloat16 g_z_h[(size_t)MTOT * 1024];          // 16 MB [b][i][d*256+f]
__device__ __align__(16) __nv_bfloat16 g_z_l[(size_t)MTOT * 1024];          // 16 MB
__device__ __align__(16) __nv_bfloat16 g_wt_h[OUTD * 1024];                 // 0.5 MB [o][d*256+f]
__device__ __align__(16) __nv_bfloat16 g_wt_l[OUTD * 1024];

// ---------------- helpers ----------------
__device__ __forceinline__ uint32_t smem_u32(const void* p) {
    uint32_t a;
    asm("{ .reg .u64 t; cvta.to.shared.u64 t, %1; cvt.u32.u64 %0, t; }" : "=r"(a) : "l"(p));
    return a;
}
__device__ __forceinline__ float warpSum(float v) {
    #pragma unroll
    for (int o = 16; o; o >>= 1) v += __shfl_xor_sync(0xffffffffu, v, o);
    return v;
}
__device__ __forceinline__ void split_bf16(float v, __nv_bfloat16& h, __nv_bfloat16& l) {
    h = __float2bfloat16(v);
    l = __float2bfloat16(v - __bfloat162float(h));
}

#define LDSM_X4(r0, r1, r2, r3, addr)                                           \
    asm volatile("ldmatrix.sync.aligned.m8n8.x4.shared.b16 {%0,%1,%2,%3}, [%4];"\
                 : "=r"(r0), "=r"(r1), "=r"(r2), "=r"(r3) : "r"(addr))

__device__ __forceinline__ void mma16816(float c[4], const uint32_t a[4],
                                         uint32_t b0, uint32_t b1) {
    asm volatile(
        "mma.sync.aligned.m16n8k16.row.col.f32.bf16.bf16.f32 "
        "{%0,%1,%2,%3}, {%4,%5,%6,%7}, {%8,%9}, {%0,%1,%2,%3};"
        : "+f"(c[0]), "+f"(c[1]), "+f"(c[2]), "+f"(c[3])
        : "r"(a[0]), "r"(a[1]), "r"(a[2]), "r"(a[3]), "r"(b0), "r"(b1));
}

// ---------------- prep: w_src/w_dst (head 1) + Wt = transposed split Wsum ----------------
__global__ void prep_kernel(const float* __restrict__ W, const float* __restrict__ a) {
    int d = blockIdx.x >> 8;
    int f = blockIdx.x & 255;
    int o = threadIdx.x;

    float w0 = W[((size_t)(d * 2 + 0) * FIN + f) * OUTD + o];
    float w1 = W[((size_t)(d * 2 + 1) * FIN + f) * OUTD + o];
    float wsum = w0 + w1;
    __nv_bfloat16 h, l;
    split_bf16(wsum, h, l);
    size_t wo = (size_t)o * 1024 + d * 256 + f;   // [o][d*256+f]
    g_wt_h[wo] = h;
    g_wt_l[wo] = l;

    float a_s = a[(d * 2 + 1) * (2 * OUTD) + o];
    float a_d = a[(d * 2 + 1) * (2 * OUTD) + OUTD + o];
    float s1 = warpSum(w1 * a_s);
    float s2 = warpSum(w1 * a_d);
    __shared__ float r1[8], r2[8];
    int lane = threadIdx.x & 31, wid = threadIdx.x >> 5;
    if (lane == 0) { r1[wid] = s1; r2[wid] = s2; }
    __syncthreads();
    if (threadIdx.x == 0) {
        float t1 = 0.f, t2 = 0.f;
        #pragma unroll
        for (int w = 0; w < 8; w++) { t1 += r1[w]; t2 += r2[w]; }
        g_wsrc[d * FIN + f] = t1;
        g_wdst[d * FIN + f] = t2;
    }
}

// ---------------- pack adjacency bits ----------------
__global__ void apack_kernel(const int* __restrict__ AU, const int* __restrict__ AD,
                             const int* __restrict__ AR, const int* __restrict__ AL) {
    int idx = blockIdx.x * 256 + threadIdx.x;
    unsigned m = (AU[idx] != 0 ? 1u : 0u) | (AD[idx] != 0 ? 2u : 0u) |
                 (AR[idx] != 0 ? 4u : 0u) | (AL[idx] != 0 ? 8u : 0u);
    g_Apack[idx] = (unsigned char)m;
}

// ---------------- x transpose + bf16 split: Xt[b][f][j] ----------------
__global__ void xt_kernel(const float* __restrict__ x) {
    __shared__ float tile[32][33];
    int j0 = blockIdx.x * 32, f0 = blockIdx.y * 32, b = blockIdx.z;
    int tx = threadIdx.x, ty = threadIdx.y;
    #pragma unroll
    for (int r = 0; r < 4; r++)
        tile[ty + 8 * r][tx] = x[((size_t)(b * NN) + j0 + ty + 8 * r) * FIN + f0 + tx];
    __syncthreads();
    #pragma unroll
    for (int r = 0; r < 4; r++) {
        int f = f0 + ty + 8 * r;
        int j = j0 + tx;
        float v = tile[tx][ty + 8 * r];
        __nv_bfloat16 h, l;
        split_bf16(v, h, l);
        size_t off = ((size_t)(b * FIN) + f) * NN + j;
        g_xt_h[off] = h;
        g_xt_l[off] = l;
    }
}

// ---------------- e_src/e_dst: one warp per (d, m) ----------------
__global__ void edge_kernel(const float* __restrict__ x) {
    int w    = (blockIdx.x * blockDim.x + threadIdx.x) >> 5;
    int lane = threadIdx.x & 31;
    int d = w >> 13;
    int m = w & 8191;
    const float* xr = x + (size_t)m * FIN;
    float s1 = 0.f, s2 = 0.f;
    #pragma unroll
    for (int it = 0; it < 8; it++) {
        int k = lane + 32 * it;
        float xv = xr[k];
        s1 += xv * g_wsrc[d * FIN + k];
        s2 += xv * g_wdst[d * FIN + k];
    }
    s1 = warpSum(s1);
    s2 = warpSum(s2);
    if (lane == 0) { g_esrc[w] = s1; g_edst[w] = s2; }
}

// ---------------- softmax over j; emits split-bf16 alpha ----------------
__global__ void softmax_kernel() {
    int bid = blockIdx.x;
    int b = bid >> 10;
    int i = bid & 1023;
    int t = threadIdx.x;
    int lane = t & 31, wid = t >> 5;

    __shared__ float s_esrc[4];
    __shared__ float sred[8];
    __shared__ float sbcast;

    if (t < 4) s_esrc[t] = g_esrc[t * MTOT + bid];
    __syncthreads();

    const float NEGINF = -CUDART_INF_F;
    float ev[4];
    float lmax = NEGINF;
    #pragma unroll
    for (int s = 0; s < 4; s++) {
        int j = t + 256 * s;
        unsigned m = g_Apack[i * NN + j];
        float e = NEGINF;
        if (m) {
            int ds = 31 - __clz(m);
            float v = s_esrc[ds] + g_edst[ds * MTOT + b * NN + j];
            e = v > 0.f ? v : 0.01f * v;
        }
        ev[s] = e;
        lmax = fmaxf(lmax, e);
    }
    #pragma unroll
    for (int o = 16; o; o >>= 1) lmax = fmaxf(lmax, __shfl_xor_sync(0xffffffffu, lmax, o));
    if (lane == 0) sred[wid] = lmax;
    __syncthreads();
    if (t == 0) {
        float v = sred[0];
        #pragma unroll
        for (int w = 1; w < 8; w++) v = fmaxf(v, sred[w]);
        sbcast = v;
    }
    __syncthreads();
    float rmax = sbcast;
    __syncthreads();

    float ex[4];
    float lsum = 0.f;
    #pragma unroll
    for (int s = 0; s < 4; s++) {
        float e = ev[s];
        float xx = (e == NEGINF) ? 0.f : __expf(e - rmax);
        ex[s] = xx;
        lsum += xx;
    }
    lsum = warpSum(lsum);
    if (lane == 0) sred[wid] = lsum;
    __syncthreads();
    if (t == 0) {
        float v = 0.f;
        #pragma unroll
        for (int w = 0; w < 8; w++) v += sred[w];
        sbcast = 1.f / v;
    }
    __syncthreads();
    float inv = sbcast;
    #pragma unroll
    for (int s = 0; s < 4; s++) {
        float av = ex[s] * inv;
        __nv_bfloat16 h, l;
        split_bf16(av, h, l);
        size_t off = (size_t)bid * NN + t + 256 * s;
        g_alpha_h[off] = h;
        g_alpha_l[off] = l;
    }
}

// ---------------- HMMA split-bf16 GEMM ----------------
// MODE 0: per (b, d, mtile, ntile): Z128x128[i, f] = sum_j (alpha*bit_d)[i,j] * xt[f,j]
//         epilogue -> split bf16 to g_z at [b][i][d*256+f]
// MODE 1: out128x128[i, o] = 0.5 * sum_dk z[i,dk] * wt[o,dk]
// Both operands row-major with K contiguous, row stride 1024 elements.
// CTA: 256 threads (8 warps as 4Mx2N), tile M=128, N=128, Kc=32, K=1024.
// smem row stride 80B (5x16B) -> conflict-free ldmatrix.
#define KCHUNKS 32
#define ROWELT  40   // bf16 per smem row (80 B)

template <int MODE>
__global__ void __launch_bounds__(256, 1) gemm_mma(float* __restrict__ out) {
    __shared__ __align__(16) __nv_bfloat16 shA_h[128 * ROWELT];
    __shared__ __align__(16) __nv_bfloat16 shA_l[128 * ROWELT];
    __shared__ __align__(16) __nv_bfloat16 shB_h[128 * ROWELT];
    __shared__ __align__(16) __nv_bfloat16 shB_l[128 * ROWELT];

    int t = threadIdx.x, lane = t & 31, wid = t >> 5;
    int mtile = blockIdx.x, ntile = blockIdx.y, z = blockIdx.z;
    int b, d;
    if (MODE == 0) { b = z >> 2; d = z & 3; } else { b = z; d = 0; }
    int i0 = mtile * 128;
    int n0 = ntile * 128;

    const __nv_bfloat16 *a_h, *a_l, *b_h, *b_l;
    if (MODE == 0) {
        a_h = g_alpha_h + ((size_t)(b * NN) + i0) * NN;
        a_l = g_alpha_l + ((size_t)(b * NN) + i0) * NN;
        b_h = g_xt_h + (size_t)b * FIN * NN + (size_t)n0 * NN;
        b_l = g_xt_l + (size_t)b * FIN * NN + (size_t)n0 * NN;
    } else {
        a_h = g_z_h + ((size_t)(b * NN) + i0) * 1024;
        a_l = g_z_l + ((size_t)(b * NN) + i0) * 1024;
        b_h = g_wt_h + (size_t)n0 * 1024;
        b_l = g_wt_l + (size_t)n0 * 1024;
    }

    // warp tile: M=32 at m_w, N=64 at n_w
    int m_w = (wid >> 1) * 32;
    int n_w = (wid & 1) * 64;

    uint32_t uA_h = smem_u32(shA_h), uA_l = smem_u32(shA_l);
    uint32_t uB_h = smem_u32(shB_h), uB_l = smem_u32(shB_l);

    float acc[2][8][4] = {};

    // chunk decomposition: 512 16B-chunks per 128x32 tile; thread handles c and c+256
    int c1 = t, c2 = t + 256;
    int r1 = c1 >> 2, ch1 = c1 & 3;
    int r2 = c2 >> 2, ch2 = c2 & 3;
    uint32_t so1 = (uint32_t)(r1 * 80 + ch1 * 16);
    uint32_t so2 = (uint32_t)(r2 * 80 + ch2 * 16);

    uint4 Ah1, Al1, Ah2, Al2, Bh1, Bl1, Bh2, Bl2;
    unsigned long long M1 = 0, M2 = 0;

    // initial load (k0 = 0)
    {
        size_t o1 = (size_t)r1 * 1024 + ch1 * 8;
        size_t o2 = (size_t)r2 * 1024 + ch2 * 8;
        Ah1 = *(const uint4*)(a_h + o1); Al1 = *(const uint4*)(a_l + o1);
        Ah2 = *(const uint4*)(a_h + o2); Al2 = *(const uint4*)(a_l + o2);
        Bh1 = *(const uint4*)(b_h + o1); Bl1 = *(const uint4*)(b_l + o1);
        Bh2 = *(const uint4*)(b_h + o2); Bl2 = *(const uint4*)(b_l + o2);
        if (MODE == 0) {
            M1 = *(const unsigned long long*)(g_Apack + (size_t)(i0 + r1) * NN + ch1 * 8);
            M2 = *(const unsigned long long*)(g_Apack + (size_t)(i0 + r2) * NN + ch2 * 8);
        }
    }

    #pragma unroll 1
    for (int kc = 0; kc < KCHUNKS; kc++) {
        __syncthreads();   // previous chunk's MMAs done reading smem
        // ---- store staged regs to smem (apply mask for MODE 0 A) ----
        if (MODE == 0) {
            unsigned short* hs1 = (unsigned short*)&Ah1;
            unsigned short* ls1 = (unsigned short*)&Al1;
            unsigned short* hs2 = (unsigned short*)&Ah2;
            unsigned short* ls2 = (unsigned short*)&Al2;
            #pragma unroll
            for (int e = 0; e < 8; e++) {
                if (!((M1 >> (8 * e + d)) & 1ull)) { hs1[e] = 0; ls1[e] = 0; }
                if (!((M2 >> (8 * e + d)) & 1ull)) { hs2[e] = 0; ls2[e] = 0; }
            }
        }
        *(uint4*)((char*)shA_h + so1) = Ah1;  *(uint4*)((char*)shA_l + so1) = Al1;
        *(uint4*)((char*)shA_h + so2) = Ah2;  *(uint4*)((char*)shA_l + so2) = Al2;
        *(uint4*)((char*)shB_h + so1) = Bh1;  *(uint4*)((char*)shB_l + so1) = Bl1;
        *(uint4*)((char*)shB_h + so2) = Bh2;  *(uint4*)((char*)shB_l + so2) = Bl2;
        __syncthreads();

        // ---- prefetch next chunk into regs (global latency hidden by MMAs) ----
        if (kc + 1 < KCHUNKS) {
            int k0 = (kc + 1) * 32;
            size_t o1 = (size_t)r1 * 1024 + k0 + ch1 * 8;
            size_t o2 = (size_t)r2 * 1024 + k0 + ch2 * 8;
            Ah1 = *(const uint4*)(a_h + o1); Al1 = *(const uint4*)(a_l + o1);
            Ah2 = *(const uint4*)(a_h + o2); Al2 = *(const uint4*)(a_l + o2);
            Bh1 = *(const uint4*)(b_h + o1); Bl1 = *(const uint4*)(b_l + o1);
            Bh2 = *(const uint4*)(b_h + o2); Bl2 = *(const uint4*)(b_l + o2);
            if (MODE == 0) {
                M1 = *(const unsigned long long*)(g_Apack + (size_t)(i0 + r1) * NN + k0 + ch1 * 8);
                M2 = *(const unsigned long long*)(g_Apack + (size_t)(i0 + r2) * NN + k0 + ch2 * 8);
            }
        }

        // ---- MMA over current smem chunk: 2 k16 steps ----
        #pragma unroll
        for (int s = 0; s < 2; s++) {
            uint32_t ah[2][4], al[2][4];
            #pragma unroll
            for (int mi = 0; mi < 2; mi++) {
                uint32_t off = (uint32_t)((m_w + mi * 16 + (lane & 15)) * 80 +
                                          s * 32 + (lane >> 4) * 16);
                LDSM_X4(ah[mi][0], ah[mi][1], ah[mi][2], ah[mi][3], uA_h + off);
                LDSM_X4(al[mi][0], al[mi][1], al[mi][2], al[mi][3], uA_l + off);
            }
            uint32_t bh[4][4], bl[4][4];
            #pragma unroll
            for (int p = 0; p < 4; p++) {
                uint32_t off = (uint32_t)((n_w + p * 16 + (lane & 15)) * 80 +
                                          s * 32 + (lane >> 4) * 16);
                LDSM_X4(bh[p][0], bh[p][1], bh[p][2], bh[p][3], uB_h + off);
                LDSM_X4(bl[p][0], bl[p][1], bl[p][2], bl[p][3], uB_l + off);
            }
            #pragma unroll
            for (int mi = 0; mi < 2; mi++) {
                #pragma unroll
                for (int p = 0; p < 4; p++) {
                    mma16816(acc[mi][2 * p],     ah[mi], bh[p][0], bh[p][2]);
                    mma16816(acc[mi][2 * p],     ah[mi], bl[p][0], bl[p][2]);
                    mma16816(acc[mi][2 * p],     al[mi], bh[p][0], bh[p][2]);
                    mma16816(acc[mi][2 * p + 1], ah[mi], bh[p][1], bh[p][3]);
                    mma16816(acc[mi][2 * p + 1], ah[mi], bl[p][1], bl[p][3]);
                    mma16816(acc[mi][2 * p + 1], al[mi], bh[p][1], bh[p][3]);
                }
            }
        }
    }

    // ---- epilogue ----
    #pragma unroll
    for (int mi = 0; mi < 2; mi++) {
        #pragma unroll
        for (int ni = 0; ni < 8; ni++) {
            int col = n_w + ni * 8 + (lane & 3) * 2;
            #pragma unroll
            for (int hh = 0; hh < 2; hh++) {
                int row = m_w + mi * 16 + (lane >> 2) + hh * 8;
                float v0 = acc[mi][ni][hh * 2 + 0];
                float v1 = acc[mi][ni][hh * 2 + 1];
                if (MODE == 0) {
                    __nv_bfloat16 h0, l0, h1, l1;
                    split_bf16(v0, h0, l0);
                    split_bf16(v1, h1, l1);
                    unsigned hp = ((unsigned)__bfloat16_as_ushort(h1) << 16) |
                                  __bfloat16_as_ushort(h0);
                    unsigned lp = ((unsigned)__bfloat16_as_ushort(l1) << 16) |
                                  __bfloat16_as_ushort(l0);
                    size_t zoff = ((size_t)(b * NN) + i0 + row) * 1024 + d * 256 + n0 + col;
                    *(unsigned*)&g_z_h[zoff] = hp;
                    *(unsigned*)&g_z_l[zoff] = lp;
                } else {
                    size_t ooff = ((size_t)(b * NN) + i0 + row) * 256 + n0 + col;
                    float2 v = make_float2(0.5f * v0, 0.5f * v1);
                    *(float2*)&out[ooff] = v;
                }
            }
        }
    }
}

// ---------------- launch ----------------
extern "C" void kernel_launch(void* const* d_in, const int* in_sizes, int n_in,
                              void* d_out, int out_size) {
    const float* x  = (const float*)d_in[0];
    const int*   AU = (const int*)d_in[1];
    const int*   AD = (const int*)d_in[2];
    const int*   AR = (const int*)d_in[3];
    const int*   AL = (const int*)d_in[4];
    const float* W  = (const float*)d_in[5];
    const float* a  = (const float*)d_in[6];
    float* out = (float*)d_out;

    prep_kernel<<<DD * FIN, 256>>>(W, a);
    apack_kernel<<<(NN * NN) / 256, 256>>>(AU, AD, AR, AL);
    xt_kernel<<<dim3(NN / 32, FIN / 32, BB), dim3(32, 8)>>>(x);
    edge_kernel<<<(DD * MTOT) / 8, 256>>>(x);
    softmax_kernel<<<MTOT, 256>>>();
    gemm_mma<0><<<dim3(8, 2, BB * DD), 256>>>(out);
    gemm_mma<1><<<dim3(8, 2, BB), 256>>>(out);
}

// round 9
// speedup vs baseline: 2.5038x; 1.0694x over previous
#include <cuda_runtime.h>
#include <cuda_bf16.h>
#include <math_constants.h>
#include <cstdint>

// Problem constants
#define BB   8
#define NN   1024
#define FIN  256
#define OUTD 256
#define DD   4
#define MTOT (BB * NN)   // 8192

// ---------------- scratch (static device globals; no dynamic alloc) ----------------
__device__ float g_wsrc[DD * FIN];
__device__ float g_wdst[DD * FIN];
__device__ float g_esrc[DD * MTOT];
__device__ float g_edst[DD * MTOT];
__device__ __align__(16) unsigned char g_Apack[NN * NN];                      // 1 MB
__device__ __align__(16) __nv_bfloat16 g_ma_h[(size_t)DD * MTOT * NN];        // 64 MB masked alpha hi
__device__ __align__(16) __nv_bfloat16 g_ma_l[(size_t)DD * MTOT * NN];        // 64 MB masked alpha lo
__device__ __align__(16) __nv_bfloat16 g_xt_h[BB * FIN * NN];                 // 4 MB  [b][f][j]
__device__ __align__(16) __nv_bfloat16 g_xt_l[BB * FIN * NN];                 // 4 MB
__device__ __align__(16) __nv_bfloat16 g_z_h[(size_t)MTOT * 1024];            // 16 MB [b][i][d*256+f]
__device__ __align__(16) __nv_bfloat16 g_z_l[(size_t)MTOT * 1024];            // 16 MB
__device__ __align__(16) __nv_bfloat16 g_wt_h[OUTD * 1024];                   // 0.5 MB [o][d*256+f]
__device__ __align__(16) __nv_bfloat16 g_wt_l[OUTD * 1024];

// ---------------- helpers ----------------
__device__ __forceinline__ uint32_t smem_u32(const void* p) {
    uint32_t a;
    asm("{ .reg .u64 t; cvta.to.shared.u64 t, %1; cvt.u32.u64 %0, t; }" : "=r"(a) : "l"(p));
    return a;
}
__device__ __forceinline__ float warpSum(float v) {
    #pragma unroll
    for (int o = 16; o; o >>= 1) v += __shfl_xor_sync(0xffffffffu, v, o);
    return v;
}
__device__ __forceinline__ void split_bf16(float v, __nv_bfloat16& h, __nv_bfloat16& l) {
    h = __float2bfloat16(v);
    l = __float2bfloat16(v - __bfloat162float(h));
}

#define LDSM_X4(r0, r1, r2, r3, addr)                                           \
    asm volatile("ldmatrix.sync.aligned.m8n8.x4.shared.b16 {%0,%1,%2,%3}, [%4];"\
                 : "=r"(r0), "=r"(r1), "=r"(r2), "=r"(r3) : "r"(addr))

#define CP16(dst, src)                                                          \
    asm volatile("cp.async.cg.shared.global [%0], [%1], 16;"                    \
                 :: "r"(dst), "l"(src))
#define CP_COMMIT() asm volatile("cp.async.commit_group;" ::: "memory")
#define CP_WAIT1()  asm volatile("cp.async.wait_group 1;" ::: "memory")
#define CP_WAIT0()  asm volatile("cp.async.wait_group 0;" ::: "memory")

__device__ __forceinline__ void mma16816(float c[4], const uint32_t a[4],
                                         uint32_t b0, uint32_t b1) {
    asm volatile(
        "mma.sync.aligned.m16n8k16.row.col.f32.bf16.bf16.f32 "
        "{%0,%1,%2,%3}, {%4,%5,%6,%7}, {%8,%9}, {%0,%1,%2,%3};"
        : "+f"(c[0]), "+f"(c[1]), "+f"(c[2]), "+f"(c[3])
        : "r"(a[0]), "r"(a[1]), "r"(a[2]), "r"(a[3]), "r"(b0), "r"(b1));
}

// ---------------- prep: w_src/w_dst (head 1) + Wt = transposed split Wsum ----------------
__global__ void prep_kernel(const float* __restrict__ W, const float* __restrict__ a) {
    int d = blockIdx.x >> 8;
    int f = blockIdx.x & 255;
    int o = threadIdx.x;

    float w0 = W[((size_t)(d * 2 + 0) * FIN + f) * OUTD + o];
    float w1 = W[((size_t)(d * 2 + 1) * FIN + f) * OUTD + o];
    float wsum = w0 + w1;
    __nv_bfloat16 h, l;
    split_bf16(wsum, h, l);
    size_t wo = (size_t)o * 1024 + d * 256 + f;   // [o][d*256+f]
    g_wt_h[wo] = h;
    g_wt_l[wo] = l;

    float a_s = a[(d * 2 + 1) * (2 * OUTD) + o];
    float a_d = a[(d * 2 + 1) * (2 * OUTD) + OUTD + o];
    float s1 = warpSum(w1 * a_s);
    float s2 = warpSum(w1 * a_d);
    __shared__ float r1[8], r2[8];
    int lane = threadIdx.x & 31, wid = threadIdx.x >> 5;
    if (lane == 0) { r1[wid] = s1; r2[wid] = s2; }
    __syncthreads();
    if (threadIdx.x == 0) {
        float t1 = 0.f, t2 = 0.f;
        #pragma unroll
        for (int w = 0; w < 8; w++) { t1 += r1[w]; t2 += r2[w]; }
        g_wsrc[d * FIN + f] = t1;
        g_wdst[d * FIN + f] = t2;
    }
}

// ---------------- pack adjacency bits ----------------
__global__ void apack_kernel(const int* __restrict__ AU, const int* __restrict__ AD,
                             const int* __restrict__ AR, const int* __restrict__ AL) {
    int idx = blockIdx.x * 256 + threadIdx.x;
    unsigned m = (AU[idx] != 0 ? 1u : 0u) | (AD[idx] != 0 ? 2u : 0u) |
                 (AR[idx] != 0 ? 4u : 0u) | (AL[idx] != 0 ? 8u : 0u);
    g_Apack[idx] = (unsigned char)m;
}

// ---------------- x transpose + bf16 split: Xt[b][f][j] ----------------
__global__ void xt_kernel(const float* __restrict__ x) {
    __shared__ float tile[32][33];
    int j0 = blockIdx.x * 32, f0 = blockIdx.y * 32, b = blockIdx.z;
    int tx = threadIdx.x, ty = threadIdx.y;
    #pragma unroll
    for (int r = 0; r < 4; r++)
        tile[ty + 8 * r][tx] = x[((size_t)(b * NN) + j0 + ty + 8 * r) * FIN + f0 + tx];
    __syncthreads();
    #pragma unroll
    for (int r = 0; r < 4; r++) {
        int f = f0 + ty + 8 * r;
        int j = j0 + tx;
        float v = tile[tx][ty + 8 * r];
        __nv_bfloat16 h, l;
        split_bf16(v, h, l);
        size_t off = ((size_t)(b * FIN) + f) * NN + j;
        g_xt_h[off] = h;
        g_xt_l[off] = l;
    }
}

// ---------------- e_src/e_dst: one warp per m, all 4 directions ----------------
__global__ void edge_kernel(const float* __restrict__ x) {
    int wid = threadIdx.x >> 5, lane = threadIdx.x & 31;
    int m = blockIdx.x * 8 + wid;
    const float* xr = x + (size_t)m * FIN;
    float xv[8];
    #pragma unroll
    for (int it = 0; it < 8; it++) xv[it] = xr[lane + 32 * it];
    #pragma unroll
    for (int d = 0; d < DD; d++) {
        float s1 = 0.f, s2 = 0.f;
        #pragma unroll
        for (int it = 0; it < 8; it++) {
            int k = lane + 32 * it;
            s1 += xv[it] * g_wsrc[d * FIN + k];
            s2 += xv[it] * g_wdst[d * FIN + k];
        }
        s1 = warpSum(s1);
        s2 = warpSum(s2);
        if (lane == 0) { g_esrc[d * MTOT + m] = s1; g_edst[d * MTOT + m] = s2; }
    }
}

// ---------------- softmax over j; emits per-direction masked split-bf16 alpha ----------------
// grid: 8192 blocks (b*1024+i), 256 threads, thread t handles j = 4t..4t+3
__global__ void softmax_kernel() {
    int bid = blockIdx.x;
    int b = bid >> 10;
    int i = bid & 1023;
    int t = threadIdx.x;
    int lane = t & 31, wid = t >> 5;

    __shared__ float s_esrc[4];
    __shared__ float sred[8];
    __shared__ float sbcast;

    if (t < 4) s_esrc[t] = g_esrc[t * MTOT + bid];
    __syncthreads();

    unsigned mword = *(const unsigned*)(g_Apack + (size_t)i * NN + 4 * t);

    const float NEGINF = -CUDART_INF_F;
    float ev[4];
    float lmax = NEGINF;
    #pragma unroll
    for (int e = 0; e < 4; e++) {
        unsigned m = (mword >> (8 * e)) & 0xFu;
        float val = NEGINF;
        if (m) {
            int ds = 31 - __clz(m);
            float v = s_esrc[ds] + g_edst[ds * MTOT + b * NN + 4 * t + e];
            val = v > 0.f ? v : 0.01f * v;
        }
        ev[e] = val;
        lmax = fmaxf(lmax, val);
    }
    #pragma unroll
    for (int o = 16; o; o >>= 1) lmax = fmaxf(lmax, __shfl_xor_sync(0xffffffffu, lmax, o));
    if (lane == 0) sred[wid] = lmax;
    __syncthreads();
    if (t == 0) {
        float v = sred[0];
        #pragma unroll
        for (int w = 1; w < 8; w++) v = fmaxf(v, sred[w]);
        sbcast = v;
    }
    __syncthreads();
    float rmax = sbcast;
    __syncthreads();

    float ex[4];
    float lsum = 0.f;
    #pragma unroll
    for (int e = 0; e < 4; e++) {
        float val = ev[e];
        float xx = (val == NEGINF) ? 0.f : __expf(val - rmax);
        ex[e] = xx;
        lsum += xx;
    }
    lsum = warpSum(lsum);
    if (lane == 0) sred[wid] = lsum;
    __syncthreads();
    if (t == 0) {
        float v = 0.f;
        #pragma unroll
        for (int w = 0; w < 8; w++) v += sred[w];
        sbcast = 1.f / v;
    }
    __syncthreads();
    float inv = sbcast;

    #pragma unroll
    for (int d = 0; d < DD; d++) {
        unsigned short hv[4], lv[4];
        #pragma unroll
        for (int e = 0; e < 4; e++) {
            unsigned bit = (mword >> (8 * e + d)) & 1u;
            float av = bit ? ex[e] * inv : 0.f;
            __nv_bfloat16 h, l;
            split_bf16(av, h, l);
            hv[e] = __bfloat16_as_ushort(h);
            lv[e] = __bfloat16_as_ushort(l);
        }
        uint2 hp = make_uint2((unsigned)hv[0] | ((unsigned)hv[1] << 16),
                              (unsigned)hv[2] | ((unsigned)hv[3] << 16));
        uint2 lp = make_uint2((unsigned)lv[0] | ((unsigned)lv[1] << 16),
                              (unsigned)lv[2] | ((unsigned)lv[3] << 16));
        size_t off = ((size_t)d * MTOT + bid) * NN + 4 * t;
        *(uint2*)&g_ma_h[off] = hp;
        *(uint2*)&g_ma_l[off] = lp;
    }
}

// ---------------- cp.async double-buffered HMMA split-bf16 GEMM ----------------
// MODE 0: per (b, d, mtile, ntile): Z128x128[i, f] = sum_j ma_d[i,j] * xt[f,j]
// MODE 1: out128x128[i, o] = 0.5 * sum_dk z[i,dk] * wt[o,dk]
// Both operands row-major, K contiguous, row stride 1024 elements.
// CTA 256 thr (8 warps 4Mx2N), tile M=128, N=128, Kc=32, K=1024.
// smem: 2 stages x (Ah|Al|Bh|Bl), each 128 rows x 80B -> 40KB/stage, 80KB total.
#define KCHUNKS     32
#define ARR_BYTES   (128 * 80)        // 10240
#define STAGE_BYTES (4 * ARR_BYTES)   // 40960
#define GSMEM       (2 * STAGE_BYTES) // 81920

template <int MODE>
__global__ void __launch_bounds__(256, 2) gemm_cp(float* __restrict__ out) {
    extern __shared__ __align__(16) char smem[];
    uint32_t sbase = smem_u32(smem);

    int t = threadIdx.x, lane = t & 31, wid = t >> 5;
    int mtile = blockIdx.x, ntile = blockIdx.y, z = blockIdx.z;
    int b, d;
    if (MODE == 0) { b = z >> 2; d = z & 3; } else { b = z; d = 0; }
    int i0 = mtile * 128;
    int n0 = ntile * 128;

    const __nv_bfloat16 *a_h, *a_l, *b_h, *b_l;
    if (MODE == 0) {
        a_h = g_ma_h + ((size_t)d * MTOT + b * NN + i0) * NN;
        a_l = g_ma_l + ((size_t)d * MTOT + b * NN + i0) * NN;
        b_h = g_xt_h + (size_t)b * FIN * NN + (size_t)n0 * NN;
        b_l = g_xt_l + (size_t)b * FIN * NN + (size_t)n0 * NN;
    } else {
        a_h = g_z_h + ((size_t)(b * NN) + i0) * 1024;
        a_l = g_z_l + ((size_t)(b * NN) + i0) * 1024;
        b_h = g_wt_h + (size_t)n0 * 1024;
        b_l = g_wt_l + (size_t)n0 * 1024;
    }

    // per-thread cp.async chunks: c = t, t+256 over 512 16B-chunks per array
    int r1 = t >> 2,          ch1 = t & 3;
    int r2 = (t + 256) >> 2,  ch2 = (t + 256) & 3;
    uint32_t so1 = (uint32_t)(r1 * 80 + ch1 * 16);
    uint32_t so2 = (uint32_t)(r2 * 80 + ch2 * 16);

    // warp tile: M=32 at m_w, N=64 at n_w
    int m_w = (wid >> 1) * 32;
    int n_w = (wid & 1) * 64;

    float acc[2][8][4] = {};

    auto issue = [&](int stage, int k0) {
        uint32_t st = sbase + stage * STAGE_BYTES;
        size_t o1 = (size_t)r1 * 1024 + k0 + ch1 * 8;
        size_t o2 = (size_t)r2 * 1024 + k0 + ch2 * 8;
        CP16(st + so1,                 a_h + o1);
        CP16(st + so2,                 a_h + o2);
        CP16(st + ARR_BYTES + so1,     a_l + o1);
        CP16(st + ARR_BYTES + so2,     a_l + o2);
        CP16(st + 2 * ARR_BYTES + so1, b_h + o1);
        CP16(st + 2 * ARR_BYTES + so2, b_h + o2);
        CP16(st + 3 * ARR_BYTES + so1, b_l + o1);
        CP16(st + 3 * ARR_BYTES + so2, b_l + o2);
    };

    issue(0, 0);
    CP_COMMIT();
    issue(1, 32);
    CP_COMMIT();

    #pragma unroll 1
    for (int kc = 0; kc < KCHUNKS; kc++) {
        int s = kc & 1;
        if (kc == KCHUNKS - 1) CP_WAIT0(); else CP_WAIT1();
        __syncthreads();

        uint32_t uA_h = sbase + s * STAGE_BYTES;
        uint32_t uA_l = uA_h + ARR_BYTES;
        uint32_t uB_h = uA_h + 2 * ARR_BYTES;
        uint32_t uB_l = uA_h + 3 * ARR_BYTES;

        #pragma unroll
        for (int s16 = 0; s16 < 2; s16++) {
            uint32_t ah[2][4], al[2][4];
            #pragma unroll
            for (int mi = 0; mi < 2; mi++) {
                uint32_t off = (uint32_t)((m_w + mi * 16 + (lane & 15)) * 80 +
                                          s16 * 32 + (lane >> 4) * 16);
                LDSM_X4(ah[mi][0], ah[mi][1], ah[mi][2], ah[mi][3], uA_h + off);
                LDSM_X4(al[mi][0], al[mi][1], al[mi][2], al[mi][3], uA_l + off);
            }
            #pragma unroll
            for (int p = 0; p < 4; p++) {
                uint32_t off = (uint32_t)((n_w + p * 16 + (lane & 15)) * 80 +
                                          s16 * 32 + (lane >> 4) * 16);
                uint32_t bh[4], bl[4];
                LDSM_X4(bh[0], bh[1], bh[2], bh[3], uB_h + off);
                LDSM_X4(bl[0], bl[1], bl[2], bl[3], uB_l + off);
                #pragma unroll
                for (int mi = 0; mi < 2; mi++) {
                    mma16816(acc[mi][2 * p],     ah[mi], bh[0], bh[2]);
                    mma16816(acc[mi][2 * p],     ah[mi], bl[0], bl[2]);
                    mma16816(acc[mi][2 * p],     al[mi], bh[0], bh[2]);
                    mma16816(acc[mi][2 * p + 1], ah[mi], bh[1], bh[3]);
                    mma16816(acc[mi][2 * p + 1], ah[mi], bl[1], bl[3]);
                    mma16816(acc[mi][2 * p + 1], al[mi], bh[1], bh[3]);
                }
            }
        }
        __syncthreads();
        if (kc + 2 < KCHUNKS) {
            issue(s, (kc + 2) * 32);
            CP_COMMIT();
        }
    }

    // ---- epilogue ----
    #pragma unroll
    for (int mi = 0; mi < 2; mi++) {
        #pragma unroll
        for (int ni = 0; ni < 8; ni++) {
            int col = n_w + ni * 8 + (lane & 3) * 2;
            #pragma unroll
            for (int hh = 0; hh < 2; hh++) {
                int row = m_w + mi * 16 + (lane >> 2) + hh * 8;
                float v0 = acc[mi][ni][hh * 2 + 0];
                float v1 = acc[mi][ni][hh * 2 + 1];
                if (MODE == 0) {
                    __nv_bfloat16 h0, l0, h1, l1;
                    split_bf16(v0, h0, l0);
                    split_bf16(v1, h1, l1);
                    unsigned hp = ((unsigned)__bfloat16_as_ushort(h1) << 16) |
                                  __bfloat16_as_ushort(h0);
                    unsigned lp = ((unsigned)__bfloat16_as_ushort(l1) << 16) |
                                  __bfloat16_as_ushort(l0);
                    size_t zoff = ((size_t)(b * NN) + i0 + row) * 1024 + d * 256 + n0 + col;
                    *(unsigned*)&g_z_h[zoff] = hp;
                    *(unsigned*)&g_z_l[zoff] = lp;
                } else {
                    size_t ooff = ((size_t)(b * NN) + i0 + row) * 256 + n0 + col;
                    float2 v = make_float2(0.5f * v0, 0.5f * v1);
                    *(float2*)&out[ooff] = v;
                }
            }
        }
    }
}

// ---------------- launch ----------------
extern "C" void kernel_launch(void* const* d_in, const int* in_sizes, int n_in,
                              void* d_out, int out_size) {
    const float* x  = (const float*)d_in[0];
    const int*   AU = (const int*)d_in[1];
    const int*   AD = (const int*)d_in[2];
    const int*   AR = (const int*)d_in[3];
    const int*   AL = (const int*)d_in[4];
    const float* W  = (const float*)d_in[5];
    const float* a  = (const float*)d_in[6];
    float* out = (float*)d_out;

    cudaFuncSetAttribute(gemm_cp<0>, cudaFuncAttributeMaxDynamicSharedMemorySize, GSMEM);
    cudaFuncSetAttribute(gemm_cp<1>, cudaFuncAttributeMaxDynamicSharedMemorySize, GSMEM);

    prep_kernel<<<DD * FIN, 256>>>(W, a);
    apack_kernel<<<(NN * NN) / 256, 256>>>(AU, AD, AR, AL);
    xt_kernel<<<dim3(NN / 32, FIN / 32, BB), dim3(32, 8)>>>(x);
    edge_kernel<<<MTOT / 8, 256>>>(x);
    softmax_kernel<<<MTOT, 256>>>();
    gemm_cp<0><<<dim3(8, 2, BB * DD), 256, GSMEM>>>(out);
    gemm_cp<1><<<dim3(8, 2, BB), 256, GSMEM>>>(out);
}

// round 10
// speedup vs baseline: 2.6006x; 1.0387x over previous
#include <cuda_runtime.h>
#include <cuda_bf16.h>
#include <math_constants.h>
#include <cstdint>

// Problem constants
#define BB   8
#define NN   1024
#define FIN  256
#define OUTD 256
#define DD   4
#define MTOT (BB * NN)   // 8192

// ---------------- scratch (static device globals; no dynamic alloc) ----------------
__device__ float g_wsrc[DD * FIN];
__device__ float g_wdst[DD * FIN];
__device__ float g_esrc[DD * MTOT];
__device__ float g_edst[DD * MTOT];
__device__ __align__(16) unsigned char g_Apack[NN * NN];                      // 1 MB
__device__ __align__(16) uint4 g_Abits[NN * 32];                              // 0.5 MB bit-planes
__device__ __align__(16) __nv_bfloat16 g_al_h[(size_t)MTOT * NN];             // 16 MB alpha hi
__device__ __align__(16) __nv_bfloat16 g_al_l[(size_t)MTOT * NN];             // 16 MB alpha lo
__device__ __align__(16) __nv_bfloat16 g_xt_h[BB * FIN * NN];                 // 4 MB  [b][f][j]
__device__ __align__(16) __nv_bfloat16 g_xt_l[BB * FIN * NN];                 // 4 MB
__device__ __align__(16) __nv_bfloat16 g_z_h[(size_t)MTOT * 1024];            // 16 MB [b][i][d*256+f]
__device__ __align__(16) __nv_bfloat16 g_z_l[(size_t)MTOT * 1024];            // 16 MB
__device__ __align__(16) __nv_bfloat16 g_wt_h[OUTD * 1024];                   // 0.5 MB [o][d*256+f]
__device__ __align__(16) __nv_bfloat16 g_wt_l[OUTD * 1024];

// ---------------- helpers ----------------
__device__ __forceinline__ uint32_t smem_u32(const void* p) {
    uint32_t a;
    asm("{ .reg .u64 t; cvta.to.shared.u64 t, %1; cvt.u32.u64 %0, t; }" : "=r"(a) : "l"(p));
    return a;
}
__device__ __forceinline__ float warpSum(float v) {
    #pragma unroll
    for (int o = 16; o; o >>= 1) v += __shfl_xor_sync(0xffffffffu, v, o);
    return v;
}
__device__ __forceinline__ void split_bf16(float v, __nv_bfloat16& h, __nv_bfloat16& l) {
    h = __float2bfloat16(v);
    l = __float2bfloat16(v - __bfloat162float(h));
}
// expand 2 adjacency bits -> per-half 0xFFFF masks
__device__ __forceinline__ uint32_t expand2(uint32_t b) {
    return (0xFFFFu & (0u - (b & 1u))) | (0xFFFF0000u & (0u - (b >> 1)));
}

#define LDSM_X4(r0, r1, r2, r3, addr)                                           \
    asm volatile("ldmatrix.sync.aligned.m8n8.x4.shared.b16 {%0,%1,%2,%3}, [%4];"\
                 : "=r"(r0), "=r"(r1), "=r"(r2), "=r"(r3) : "r"(addr))

#define CP16(dst, src)                                                          \
    asm volatile("cp.async.cg.shared.global [%0], [%1], 16;"                    \
                 :: "r"(dst), "l"(src))
#define CP_COMMIT() asm volatile("cp.async.commit_group;" ::: "memory")
#define CP_WAIT1()  asm volatile("cp.async.wait_group 1;" ::: "memory")
#define CP_WAIT0()  asm volatile("cp.async.wait_group 0;" ::: "memory")

__device__ __forceinline__ void mma16816(float c[4], const uint32_t a[4],
                                         uint32_t b0, uint32_t b1) {
    asm volatile(
        "mma.sync.aligned.m16n8k16.row.col.f32.bf16.bf16.f32 "
        "{%0,%1,%2,%3}, {%4,%5,%6,%7}, {%8,%9}, {%0,%1,%2,%3};"
        : "+f"(c[0]), "+f"(c[1]), "+f"(c[2]), "+f"(c[3])
        : "r"(a[0]), "r"(a[1]), "r"(a[2]), "r"(a[3]), "r"(b0), "r"(b1));
}

// ---------------- prep: w_src/w_dst (head 1) + Wt = transposed split Wsum ----------------
__global__ void prep_kernel(const float* __restrict__ W, const float* __restrict__ a) {
    int d = blockIdx.x >> 8;
    int f = blockIdx.x & 255;
    int o = threadIdx.x;

    float w0 = W[((size_t)(d * 2 + 0) * FIN + f) * OUTD + o];
    float w1 = W[((size_t)(d * 2 + 1) * FIN + f) * OUTD + o];
    float wsum = w0 + w1;
    __nv_bfloat16 h, l;
    split_bf16(wsum, h, l);
    size_t wo = (size_t)o * 1024 + d * 256 + f;   // [o][d*256+f]
    g_wt_h[wo] = h;
    g_wt_l[wo] = l;

    float a_s = a[(d * 2 + 1) * (2 * OUTD) + o];
    float a_d = a[(d * 2 + 1) * (2 * OUTD) + OUTD + o];
    float s1 = warpSum(w1 * a_s);
    float s2 = warpSum(w1 * a_d);
    __shared__ float r1[8], r2[8];
    int lane = threadIdx.x & 31, wid = threadIdx.x >> 5;
    if (lane == 0) { r1[wid] = s1; r2[wid] = s2; }
    __syncthreads();
    if (threadIdx.x == 0) {
        float t1 = 0.f, t2 = 0.f;
        #pragma unroll
        for (int w = 0; w < 8; w++) { t1 += r1[w]; t2 += r2[w]; }
        g_wsrc[d * FIN + f] = t1;
        g_wdst[d * FIN + f] = t2;
    }
}

// ---------------- pack adjacency bits ----------------
__global__ void apack_kernel(const int* __restrict__ AU, const int* __restrict__ AD,
                             const int* __restrict__ AR, const int* __restrict__ AL) {
    int idx = blockIdx.x * 256 + threadIdx.x;
    unsigned m = (AU[idx] != 0 ? 1u : 0u) | (AD[idx] != 0 ? 2u : 0u) |
                 (AR[idx] != 0 ? 4u : 0u) | (AL[idx] != 0 ? 8u : 0u);
    g_Apack[idx] = (unsigned char)m;
}

// ---------------- adjacency bit-planes: g_Abits[i*32+j32].d = 32 j-bits of dir d ----------------
__global__ void abits_kernel() {
    int idx = blockIdx.x * 256 + threadIdx.x;  // 32768 = 1024 * 32
    int i = idx >> 5, j32 = idx & 31;
    const unsigned* src = (const unsigned*)(g_Apack + (size_t)i * NN + j32 * 32);
    unsigned w[4] = {0, 0, 0, 0};
    #pragma unroll
    for (int q = 0; q < 8; q++) {
        unsigned v = src[q];
        #pragma unroll
        for (int e = 0; e < 4; e++) {
            unsigned nib = (v >> (8 * e)) & 0xFu;
            #pragma unroll
            for (int d = 0; d < 4; d++)
                w[d] |= ((nib >> d) & 1u) << (q * 4 + e);
        }
    }
    g_Abits[idx] = make_uint4(w[0], w[1], w[2], w[3]);
}

// ---------------- x transpose + bf16 split: Xt[b][f][j] ----------------
__global__ void xt_kernel(const float* __restrict__ x) {
    __shared__ float tile[32][33];
    int j0 = blockIdx.x * 32, f0 = blockIdx.y * 32, b = blockIdx.z;
    int tx = threadIdx.x, ty = threadIdx.y;
    #pragma unroll
    for (int r = 0; r < 4; r++)
        tile[ty + 8 * r][tx] = x[((size_t)(b * NN) + j0 + ty + 8 * r) * FIN + f0 + tx];
    __syncthreads();
    #pragma unroll
    for (int r = 0; r < 4; r++) {
        int f = f0 + ty + 8 * r;
        int j = j0 + tx;
        float v = tile[tx][ty + 8 * r];
        __nv_bfloat16 h, l;
        split_bf16(v, h, l);
        size_t off = ((size_t)(b * FIN) + f) * NN + j;
        g_xt_h[off] = h;
        g_xt_l[off] = l;
    }
}

// ---------------- e_src/e_dst: one warp per m, all 4 directions ----------------
__global__ void edge_kernel(const float* __restrict__ x) {
    int wid = threadIdx.x >> 5, lane = threadIdx.x & 31;
    int m = blockIdx.x * 8 + wid;
    const float* xr = x + (size_t)m * FIN;
    float xv[8];
    #pragma unroll
    for (int it = 0; it < 8; it++) xv[it] = xr[lane + 32 * it];
    #pragma unroll
    for (int d = 0; d < DD; d++) {
        float s1 = 0.f, s2 = 0.f;
        #pragma unroll
        for (int it = 0; it < 8; it++) {
            int k = lane + 32 * it;
            s1 += xv[it] * g_wsrc[d * FIN + k];
            s2 += xv[it] * g_wdst[d * FIN + k];
        }
        s1 = warpSum(s1);
        s2 = warpSum(s2);
        if (lane == 0) { g_esrc[d * MTOT + m] = s1; g_edst[d * MTOT + m] = s2; }
    }
}

// ---------------- softmax over j; emits single split-bf16 alpha ----------------
__global__ void softmax_kernel() {
    int bid = blockIdx.x;
    int b = bid >> 10;
    int i = bid & 1023;
    int t = threadIdx.x;
    int lane = t & 31, wid = t >> 5;

    __shared__ float s_esrc[4];
    __shared__ float sred[8];
    __shared__ float sbcast;

    if (t < 4) s_esrc[t] = g_esrc[t * MTOT + bid];
    __syncthreads();

    unsigned mword = *(const unsigned*)(g_Apack + (size_t)i * NN + 4 * t);

    const float NEGINF = -CUDART_INF_F;
    float ev[4];
    float lmax = NEGINF;
    #pragma unroll
    for (int e = 0; e < 4; e++) {
        unsigned m = (mword >> (8 * e)) & 0xFu;
        float val = NEGINF;
        if (m) {
            int ds = 31 - __clz(m);
            float v = s_esrc[ds] + g_edst[ds * MTOT + b * NN + 4 * t + e];
            val = v > 0.f ? v : 0.01f * v;
        }
        ev[e] = val;
        lmax = fmaxf(lmax, val);
    }
    #pragma unroll
    for (int o = 16; o; o >>= 1) lmax = fmaxf(lmax, __shfl_xor_sync(0xffffffffu, lmax, o));
    if (lane == 0) sred[wid] = lmax;
    __syncthreads();
    if (t == 0) {
        float v = sred[0];
        #pragma unroll
        for (int w = 1; w < 8; w++) v = fmaxf(v, sred[w]);
        sbcast = v;
    }
    __syncthreads();
    float rmax = sbcast;
    __syncthreads();

    float ex[4];
    float lsum = 0.f;
    #pragma unroll
    for (int e = 0; e < 4; e++) {
        float val = ev[e];
        float xx = (val == NEGINF) ? 0.f : __expf(val - rmax);
        ex[e] = xx;
        lsum += xx;
    }
    lsum = warpSum(lsum);
    if (lane == 0) sred[wid] = lsum;
    __syncthreads();
    if (t == 0) {
        float v = 0.f;
        #pragma unroll
        for (int w = 0; w < 8; w++) v += sred[w];
        sbcast = 1.f / v;
    }
    __syncthreads();
    float inv = sbcast;

    unsigned short hv[4], lv[4];
    #pragma unroll
    for (int e = 0; e < 4; e++) {
        float av = ex[e] * inv;
        __nv_bfloat16 h, l;
        split_bf16(av, h, l);
        hv[e] = __bfloat16_as_ushort(h);
        lv[e] = __bfloat16_as_ushort(l);
    }
    uint2 hp = make_uint2((unsigned)hv[0] | ((unsigned)hv[1] << 16),
                          (unsigned)hv[2] | ((unsigned)hv[3] << 16));
    uint2 lp = make_uint2((unsigned)lv[0] | ((unsigned)lv[1] << 16),
                          (unsigned)lv[2] | ((unsigned)lv[3] << 16));
    size_t off = (size_t)bid * NN + 4 * t;
    *(uint2*)&g_al_h[off] = hp;
    *(uint2*)&g_al_l[off] = lp;
}

// ---------------- GEMM1: all 4 directions per CTA, in-register masking ----------------
// per (b, mtile, ntile): for d in 0..3: Z_d[64 i x 128 f] = sum_j (alpha*bit_d)[i,j] * xt[f,j]
// CTA 256 thr, 8 warps (4M x 2N): warp tile m16 x n64. acc[4][8][4].
// smem stage: Ah(64x80) | Al | Bh(128x80) | Bl | Mask(64x16B)
#define A1_BYTES  (64 * 80)            // 5120
#define B1_BYTES  (128 * 80)           // 10240
#define MK_OFF    (2 * A1_BYTES + 2 * B1_BYTES)          // 30720
#define ST1_BYTES (MK_OFF + 64 * 16)   // 31744
#define GS1       (2 * ST1_BYTES)      // 63488

__global__ void __launch_bounds__(256, 1) gemm1(void) {
    extern __shared__ __align__(16) char smem[];
    uint32_t sbase = smem_u32(smem);

    int t = threadIdx.x, lane = t & 31, wid = t >> 5;
    int mtile = blockIdx.x, ntile = blockIdx.y, b = blockIdx.z;
    int i0 = mtile * 64;
    int n0 = ntile * 128;

    const __nv_bfloat16* a_h = g_al_h + ((size_t)(b * NN) + i0) * NN;
    const __nv_bfloat16* a_l = g_al_l + ((size_t)(b * NN) + i0) * NN;
    const __nv_bfloat16* b_h = g_xt_h + (size_t)b * FIN * NN + (size_t)n0 * NN;
    const __nv_bfloat16* b_l = g_xt_l + (size_t)b * FIN * NN + (size_t)n0 * NN;

    int ra = t >> 2, cha = t & 3;            // A rows 0..63, 4 chunks
    int rb1 = t >> 2, rb2 = 64 + (t >> 2);   // B rows, 4 chunks
    uint32_t soA = (uint32_t)(ra * 80 + cha * 16);
    uint32_t soB1 = (uint32_t)(rb1 * 80 + cha * 16);
    uint32_t soB2 = (uint32_t)(rb2 * 80 + cha * 16);

    int m_w = (wid >> 1) * 16;
    int n_w = (wid & 1) * 64;

    float acc[4][8][4] = {};

    auto issue = [&](int stage, int kc) {
        uint32_t st = sbase + stage * ST1_BYTES;
        size_t oa = (size_t)ra * NN + kc * 32 + cha * 8;
        CP16(st + soA,            a_h + oa);
        CP16(st + A1_BYTES + soA, a_l + oa);
        size_t ob1 = (size_t)rb1 * NN + kc * 32 + cha * 8;
        size_t ob2 = (size_t)rb2 * NN + kc * 32 + cha * 8;
        CP16(st + 2 * A1_BYTES + soB1,            b_h + ob1);
        CP16(st + 2 * A1_BYTES + soB2,            b_h + ob2);
        CP16(st + 2 * A1_BYTES + B1_BYTES + soB1, b_l + ob1);
        CP16(st + 2 * A1_BYTES + B1_BYTES + soB2, b_l + ob2);
        if (t < 64)
            CP16(st + MK_OFF + t * 16, (const char*)&g_Abits[(size_t)(i0 + t) * 32 + kc]);
    };

    issue(0, 0);
    CP_COMMIT();
    issue(1, 1);
    CP_COMMIT();

    #pragma unroll 1
    for (int kc = 0; kc < 32; kc++) {
        int s = kc & 1;
        if (kc == 31) CP_WAIT0(); else CP_WAIT1();
        __syncthreads();

        uint32_t uAh = sbase + s * ST1_BYTES;
        uint32_t uAl = uAh + A1_BYTES;
        uint32_t uBh = uAh + 2 * A1_BYTES;
        uint32_t uBl = uBh + B1_BYTES;
        const uint4* mk = (const uint4*)(smem + s * ST1_BYTES + MK_OFF);

        int rr = m_w + (lane >> 2);
        uint4 w0 = mk[rr];
        uint4 w1 = mk[rr + 8];

        #pragma unroll
        for (int s16 = 0; s16 < 2; s16++) {
            uint32_t ah[4], al4[4];
            {
                uint32_t off = (uint32_t)((m_w + (lane & 15)) * 80 +
                                          s16 * 32 + (lane >> 4) * 16);
                LDSM_X4(ah[0], ah[1], ah[2], ah[3], uAh + off);
                LDSM_X4(al4[0], al4[1], al4[2], al4[3], uAl + off);
            }
            uint32_t bh[4][4], bl[4][4];
            #pragma unroll
            for (int p = 0; p < 4; p++) {
                uint32_t off = (uint32_t)((n_w + p * 16 + (lane & 15)) * 80 +
                                          s16 * 32 + (lane >> 4) * 16);
                LDSM_X4(bh[p][0], bh[p][1], bh[p][2], bh[p][3], uBh + off);
                LDSM_X4(bl[p][0], bl[p][1], bl[p][2], bl[p][3], uBl + off);
            }
            int sh = s16 * 16 + (lane & 3) * 2;
            #pragma unroll
            for (int d = 0; d < 4; d++) {
                unsigned wd0 = (&w0.x)[d];
                unsigned wd1 = (&w1.x)[d];
                uint32_t m0 = expand2((wd0 >> sh) & 3u);
                uint32_t m1 = expand2((wd1 >> sh) & 3u);
                uint32_t m2 = expand2((wd0 >> (sh + 8)) & 3u);
                uint32_t m3 = expand2((wd1 >> (sh + 8)) & 3u);
                uint32_t amh[4] = {ah[0] & m0, ah[1] & m1, ah[2] & m2, ah[3] & m3};
                uint32_t aml[4] = {al4[0] & m0, al4[1] & m1, al4[2] & m2, al4[3] & m3};
                #pragma unroll
                for (int p = 0; p < 4; p++) {
                    mma16816(acc[d][2 * p],     amh, bh[p][0], bh[p][2]);
                    mma16816(acc[d][2 * p],     amh, bl[p][0], bl[p][2]);
                    mma16816(acc[d][2 * p],     aml, bh[p][0], bh[p][2]);
                    mma16816(acc[d][2 * p + 1], amh, bh[p][1], bh[p][3]);
                    mma16816(acc[d][2 * p + 1], amh, bl[p][1], bl[p][3]);
                    mma16816(acc[d][2 * p + 1], aml, bh[p][1], bh[p][3]);
                }
            }
        }
        __syncthreads();
        if (kc + 2 < 32) {
            issue(s, kc + 2);
            CP_COMMIT();
        }
    }

    // ---- epilogue: split-bf16 Z stores for all 4 d ----
    #pragma unroll
    for (int d = 0; d < 4; d++) {
        #pragma unroll
        for (int ni = 0; ni < 8; ni++) {
            int col = n_w + ni * 8 + (lane & 3) * 2;
            #pragma unroll
            for (int hh = 0; hh < 2; hh++) {
                int row = m_w + (lane >> 2) + hh * 8;
                float v0 = acc[d][ni][hh * 2 + 0];
                float v1 = acc[d][ni][hh * 2 + 1];
                __nv_bfloat16 h0, l0, h1, l1;
                split_bf16(v0, h0, l0);
                split_bf16(v1, h1, l1);
                unsigned hp = ((unsigned)__bfloat16_as_ushort(h1) << 16) |
                              __bfloat16_as_ushort(h0);
                unsigned lp = ((unsigned)__bfloat16_as_ushort(l1) << 16) |
                              __bfloat16_as_ushort(l0);
                size_t zoff = ((size_t)(b * NN) + i0 + row) * 1024 + d * 256 + n0 + col;
                *(unsigned*)&g_z_h[zoff] = hp;
                *(unsigned*)&g_z_l[zoff] = lp;
            }
        }
    }
}

// ---------------- GEMM2: out = 0.5 * z @ wt^T (cp.async double-buffered) ----------------
#define KCHUNKS     32
#define ARR_BYTES   (128 * 80)        // 10240
#define STAGE_BYTES (4 * ARR_BYTES)   // 40960
#define GS2         (2 * STAGE_BYTES) // 81920

__global__ void __launch_bounds__(256, 2) gemm2(float* __restrict__ out) {
    extern __shared__ __align__(16) char smem[];
    uint32_t sbase = smem_u32(smem);

    int t = threadIdx.x, lane = t & 31, wid = t >> 5;
    int mtile = blockIdx.x, ntile = blockIdx.y, b = blockIdx.z;
    int i0 = mtile * 128;
    int n0 = ntile * 128;

    const __nv_bfloat16* a_h = g_z_h + ((size_t)(b * NN) + i0) * 1024;
    const __nv_bfloat16* a_l = g_z_l + ((size_t)(b * NN) + i0) * 1024;
    const __nv_bfloat16* b_h = g_wt_h + (size_t)n0 * 1024;
    const __nv_bfloat16* b_l = g_wt_l + (size_t)n0 * 1024;

    int r1 = t >> 2,          ch1 = t & 3;
    int r2 = (t + 256) >> 2,  ch2 = (t + 256) & 3;
    uint32_t so1 = (uint32_t)(r1 * 80 + ch1 * 16);
    uint32_t so2 = (uint32_t)(r2 * 80 + ch2 * 16);

    int m_w = (wid >> 1) * 32;
    int n_w = (wid & 1) * 64;

    float acc[2][8][4] = {};

    auto issue = [&](int stage, int k0) {
        uint32_t st = sbase + stage * STAGE_BYTES;
        size_t o1 = (size_t)r1 * 1024 + k0 + ch1 * 8;
        size_t o2 = (size_t)r2 * 1024 + k0 + ch2 * 8;
        CP16(st + so1,                 a_h + o1);
        CP16(st + so2,                 a_h + o2);
        CP16(st + ARR_BYTES + so1,     a_l + o1);
        CP16(st + ARR_BYTES + so2,     a_l + o2);
        CP16(st + 2 * ARR_BYTES + so1, b_h + o1);
        CP16(st + 2 * ARR_BYTES + so2, b_h + o2);
        CP16(st + 3 * ARR_BYTES + so1, b_l + o1);
        CP16(st + 3 * ARR_BYTES + so2, b_l + o2);
    };

    issue(0, 0);
    CP_COMMIT();
    issue(1, 32);
    CP_COMMIT();

    #pragma unroll 1
    for (int kc = 0; kc < KCHUNKS; kc++) {
        int s = kc & 1;
        if (kc == KCHUNKS - 1) CP_WAIT0(); else CP_WAIT1();
        __syncthreads();

        uint32_t uA_h = sbase + s * STAGE_BYTES;
        uint32_t uA_l = uA_h + ARR_BYTES;
        uint32_t uB_h = uA_h + 2 * ARR_BYTES;
        uint32_t uB_l = uA_h + 3 * ARR_BYTES;

        #pragma unroll
        for (int s16 = 0; s16 < 2; s16++) {
            uint32_t ah[2][4], al[2][4];
            #pragma unroll
            for (int mi = 0; mi < 2; mi++) {
                uint32_t off = (uint32_t)((m_w + mi * 16 + (lane & 15)) * 80 +
                                          s16 * 32 + (lane >> 4) * 16);
                LDSM_X4(ah[mi][0], ah[mi][1], ah[mi][2], ah[mi][3], uA_h + off);
                LDSM_X4(al[mi][0], al[mi][1], al[mi][2], al[mi][3], uA_l + off);
            }
            #pragma unroll
            for (int p = 0; p < 4; p++) {
                uint32_t off = (uint32_t)((n_w + p * 16 + (lane & 15)) * 80 +
                                          s16 * 32 + (lane >> 4) * 16);
                uint32_t bh[4], bl[4];
                LDSM_X4(bh[0], bh[1], bh[2], bh[3], uB_h + off);
                LDSM_X4(bl[0], bl[1], bl[2], bl[3], uB_l + off);
                #pragma unroll
                for (int mi = 0; mi < 2; mi++) {
                    mma16816(acc[mi][2 * p],     ah[mi], bh[0], bh[2]);
                    mma16816(acc[mi][2 * p],     ah[mi], bl[0], bl[2]);
                    mma16816(acc[mi][2 * p],     al[mi], bh[0], bh[2]);
                    mma16816(acc[mi][2 * p + 1], ah[mi], bh[1], bh[3]);
                    mma16816(acc[mi][2 * p + 1], ah[mi], bl[1], bl[3]);
                    mma16816(acc[mi][2 * p + 1], al[mi], bh[1], bh[3]);
                }
            }
        }
        __syncthreads();
        if (kc + 2 < KCHUNKS) {
            issue(s, (kc + 2) * 32);
            CP_COMMIT();
        }
    }

    #pragma unroll
    for (int mi = 0; mi < 2; mi++) {
        #pragma unroll
        for (int ni = 0; ni < 8; ni++) {
            int col = n_w + ni * 8 + (lane & 3) * 2;
            #pragma unroll
            for (int hh = 0; hh < 2; hh++) {
                int row = m_w + mi * 16 + (lane >> 2) + hh * 8;
                size_t ooff = ((size_t)(b * NN) + i0 + row) * 256 + n0 + col;
                float2 v = make_float2(0.5f * acc[mi][ni][hh * 2 + 0],
                                       0.5f * acc[mi][ni][hh * 2 + 1]);
                *(float2*)&out[ooff] = v;
            }
        }
    }
}

// ---------------- launch ----------------
extern "C" void kernel_launch(void* const* d_in, const int* in_sizes, int n_in,
                              void* d_out, int out_size) {
    const float* x  = (const float*)d_in[0];
    const int*   AU = (const int*)d_in[1];
    const int*   AD = (const int*)d_in[2];
    const int*   AR = (const int*)d_in[3];
    const int*   AL = (const int*)d_in[4];
    const float* W  = (const float*)d_in[5];
    const float* a  = (const float*)d_in[6];
    float* out = (float*)d_out;

    cudaFuncSetAttribute(gemm1, cudaFuncAttributeMaxDynamicSharedMemorySize, GS1);
    cudaFuncSetAttribute(gemm2, cudaFuncAttributeMaxDynamicSharedMemorySize, GS2);

    prep_kernel<<<DD * FIN, 256>>>(W, a);
    apack_kernel<<<(NN * NN) / 256, 256>>>(AU, AD, AR, AL);
    abits_kernel<<<(NN * 32) / 256, 256>>>();
    xt_kernel<<<dim3(NN / 32, FIN / 32, BB), dim3(32, 8)>>>(x);
    edge_kernel<<<MTOT / 8, 256>>>(x);
    softmax_kernel<<<MTOT, 256>>>();
    gemm1<<<dim3(16, 2, BB), 256, GS1>>>();
    gemm2<<<dim3(8, 2, BB), 256, GS2>>>(out);
}

// round 11
// speedup vs baseline: 3.2628x; 1.2546x over previous
#include <cuda_runtime.h>
#include <cuda_fp16.h>
#include <math_constants.h>
#include <cstdint>

// Problem constants
#define BB   8
#define NN   1024
#define FIN  256
#define OUTD 256
#define DD   4
#define MTOT (BB * NN)   // 8192

// ---------------- scratch (static device globals; no dynamic alloc) ----------------
__device__ float g_wsrc[DD * FIN];
__device__ float g_wdst[DD * FIN];
__device__ float g_esrc[DD * MTOT];
__device__ float g_edst[DD * MTOT];
__device__ __align__(16) unsigned char g_Apack[NN * NN];              // 1 MB
__device__ __align__(16) uint4 g_Abits[NN * 32];                      // 0.5 MB bit-planes
__device__ __align__(16) __half g_al[(size_t)MTOT * NN];              // 16 MB alpha (fp16)
__device__ __align__(16) __half g_xt_h[BB * FIN * NN];                // 4 MB  [b][f][j] hi
__device__ __align__(16) __half g_xt_l[BB * FIN * NN];                // 4 MB  lo
__device__ __align__(16) __half g_z_h[(size_t)MTOT * 1024];           // 16 MB [b][i][d*256+f]
__device__ __align__(16) __half g_z_l[(size_t)MTOT * 1024];           // 16 MB
__device__ __align__(16) __half g_wt[OUTD * 1024];                    // 0.5 MB [o][d*256+f]

// ---------------- helpers ----------------
__device__ __forceinline__ uint32_t smem_u32(const void* p) {
    uint32_t a;
    asm("{ .reg .u64 t; cvta.to.shared.u64 t, %1; cvt.u32.u64 %0, t; }" : "=r"(a) : "l"(p));
    return a;
}
__device__ __forceinline__ float warpSum(float v) {
    #pragma unroll
    for (int o = 16; o; o >>= 1) v += __shfl_xor_sync(0xffffffffu, v, o);
    return v;
}
__device__ __forceinline__ void split_h16(float v, __half& h, __half& l) {
    h = __float2half_rn(v);
    l = __float2half_rn(v - __half2float(h));
}
// expand 2 adjacency bits -> per-half 0xFFFF masks
__device__ __forceinline__ uint32_t expand2(uint32_t b) {
    return (0xFFFFu & (0u - (b & 1u))) | (0xFFFF0000u & (0u - (b >> 1)));
}

#define LDSM_X4(r0, r1, r2, r3, addr)                                           \
    asm volatile("ldmatrix.sync.aligned.m8n8.x4.shared.b16 {%0,%1,%2,%3}, [%4];"\
                 : "=r"(r0), "=r"(r1), "=r"(r2), "=r"(r3) : "r"(addr))

#define CP16(dst, src)                                                          \
    asm volatile("cp.async.cg.shared.global [%0], [%1], 16;"                    \
                 :: "r"(dst), "l"(src))
#define CP_COMMIT() asm volatile("cp.async.commit_group;" ::: "memory")
#define CP_WAIT1()  asm volatile("cp.async.wait_group 1;" ::: "memory")
#define CP_WAIT0()  asm volatile("cp.async.wait_group 0;" ::: "memory")

__device__ __forceinline__ void mma16816(float c[4], const uint32_t a[4],
                                         uint32_t b0, uint32_t b1) {
    asm volatile(
        "mma.sync.aligned.m16n8k16.row.col.f32.f16.f16.f32 "
        "{%0,%1,%2,%3}, {%4,%5,%6,%7}, {%8,%9}, {%0,%1,%2,%3};"
        : "+f"(c[0]), "+f"(c[1]), "+f"(c[2]), "+f"(c[3])
        : "r"(a[0]), "r"(a[1]), "r"(a[2]), "r"(a[3]), "r"(b0), "r"(b1));
}

// ---------------- prep: w_src/w_dst (head 1) + Wt = transposed fp16 Wsum ----------------
__global__ void prep_kernel(const float* __restrict__ W, const float* __restrict__ a) {
    int d = blockIdx.x >> 8;
    int f = blockIdx.x & 255;
    int o = threadIdx.x;

    float w0 = W[((size_t)(d * 2 + 0) * FIN + f) * OUTD + o];
    float w1 = W[((size_t)(d * 2 + 1) * FIN + f) * OUTD + o];
    float wsum = w0 + w1;
    size_t wo = (size_t)o * 1024 + d * 256 + f;   // [o][d*256+f]
    g_wt[wo] = __float2half_rn(wsum);

    float a_s = a[(d * 2 + 1) * (2 * OUTD) + o];
    float a_d = a[(d * 2 + 1) * (2 * OUTD) + OUTD + o];
    float s1 = warpSum(w1 * a_s);
    float s2 = warpSum(w1 * a_d);
    __shared__ float r1[8], r2[8];
    int lane = threadIdx.x & 31, wid = threadIdx.x >> 5;
    if (lane == 0) { r1[wid] = s1; r2[wid] = s2; }
    __syncthreads();
    if (threadIdx.x == 0) {
        float t1 = 0.f, t2 = 0.f;
        #pragma unroll
        for (int w = 0; w < 8; w++) { t1 += r1[w]; t2 += r2[w]; }
        g_wsrc[d * FIN + f] = t1;
        g_wdst[d * FIN + f] = t2;
    }
}

// ---------------- pack adjacency bits ----------------
__global__ void apack_kernel(const int* __restrict__ AU, const int* __restrict__ AD,
                             const int* __restrict__ AR, const int* __restrict__ AL) {
    int idx = blockIdx.x * 256 + threadIdx.x;
    unsigned m = (AU[idx] != 0 ? 1u : 0u) | (AD[idx] != 0 ? 2u : 0u) |
                 (AR[idx] != 0 ? 4u : 0u) | (AL[idx] != 0 ? 8u : 0u);
    g_Apack[idx] = (unsigned char)m;
}

// ---------------- adjacency bit-planes: g_Abits[i*32+j32].d = 32 j-bits of dir d ----------------
__global__ void abits_kernel() {
    int idx = blockIdx.x * 256 + threadIdx.x;  // 32768 = 1024 * 32
    int i = idx >> 5, j32 = idx & 31;
    const unsigned* src = (const unsigned*)(g_Apack + (size_t)i * NN + j32 * 32);
    unsigned w[4] = {0, 0, 0, 0};
    #pragma unroll
    for (int q = 0; q < 8; q++) {
        unsigned v = src[q];
        #pragma unroll
        for (int e = 0; e < 4; e++) {
            unsigned nib = (v >> (8 * e)) & 0xFu;
            #pragma unroll
            for (int d = 0; d < 4; d++)
                w[d] |= ((nib >> d) & 1u) << (q * 4 + e);
        }
    }
    g_Abits[idx] = make_uint4(w[0], w[1], w[2], w[3]);
}

// ---------------- x transpose + fp16 split: Xt[b][f][j] ----------------
__global__ void xt_kernel(const float* __restrict__ x) {
    __shared__ float tile[32][33];
    int j0 = blockIdx.x * 32, f0 = blockIdx.y * 32, b = blockIdx.z;
    int tx = threadIdx.x, ty = threadIdx.y;
    #pragma unroll
    for (int r = 0; r < 4; r++)
        tile[ty + 8 * r][tx] = x[((size_t)(b * NN) + j0 + ty + 8 * r) * FIN + f0 + tx];
    __syncthreads();
    #pragma unroll
    for (int r = 0; r < 4; r++) {
        int f = f0 + ty + 8 * r;
        int j = j0 + tx;
        float v = tile[tx][ty + 8 * r];
        __half h, l;
        split_h16(v, h, l);
        size_t off = ((size_t)(b * FIN) + f) * NN + j;
        g_xt_h[off] = h;
        g_xt_l[off] = l;
    }
}

// ---------------- e_src/e_dst: one warp per m, all 4 directions ----------------
__global__ void edge_kernel(const float* __restrict__ x) {
    int wid = threadIdx.x >> 5, lane = threadIdx.x & 31;
    int m = blockIdx.x * 8 + wid;
    const float* xr = x + (size_t)m * FIN;
    float xv[8];
    #pragma unroll
    for (int it = 0; it < 8; it++) xv[it] = xr[lane + 32 * it];
    #pragma unroll
    for (int d = 0; d < DD; d++) {
        float s1 = 0.f, s2 = 0.f;
        #pragma unroll
        for (int it = 0; it < 8; it++) {
            int k = lane + 32 * it;
            s1 += xv[it] * g_wsrc[d * FIN + k];
            s2 += xv[it] * g_wdst[d * FIN + k];
        }
        s1 = warpSum(s1);
        s2 = warpSum(s2);
        if (lane == 0) { g_esrc[d * MTOT + m] = s1; g_edst[d * MTOT + m] = s2; }
    }
}

// ---------------- softmax over j; emits single fp16 alpha ----------------
__global__ void softmax_kernel() {
    int bid = blockIdx.x;
    int b = bid >> 10;
    int i = bid & 1023;
    int t = threadIdx.x;
    int lane = t & 31, wid = t >> 5;

    __shared__ float s_esrc[4];
    __shared__ float sred[8];
    __shared__ float sbcast;

    if (t < 4) s_esrc[t] = g_esrc[t * MTOT + bid];
    __syncthreads();

    unsigned mword = *(const unsigned*)(g_Apack + (size_t)i * NN + 4 * t);

    const float NEGINF = -CUDART_INF_F;
    float ev[4];
    float lmax = NEGINF;
    #pragma unroll
    for (int e = 0; e < 4; e++) {
        unsigned m = (mword >> (8 * e)) & 0xFu;
        float val = NEGINF;
        if (m) {
            int ds = 31 - __clz(m);
            float v = s_esrc[ds] + g_edst[ds * MTOT + b * NN + 4 * t + e];
            val = v > 0.f ? v : 0.01f * v;
        }
        ev[e] = val;
        lmax = fmaxf(lmax, val);
    }
    #pragma unroll
    for (int o = 16; o; o >>= 1) lmax = fmaxf(lmax, __shfl_xor_sync(0xffffffffu, lmax, o));
    if (lane == 0) sred[wid] = lmax;
    __syncthreads();
    if (t == 0) {
        float v = sred[0];
        #pragma unroll
        for (int w = 1; w < 8; w++) v = fmaxf(v, sred[w]);
        sbcast = v;
    }
    __syncthreads();
    float rmax = sbcast;
    __syncthreads();

    float ex[4];
    float lsum = 0.f;
    #pragma unroll
    for (int e = 0; e < 4; e++) {
        float val = ev[e];
        float xx = (val == NEGINF) ? 0.f : __expf(val - rmax);
        ex[e] = xx;
        lsum += xx;
    }
    lsum = warpSum(lsum);
    if (lane == 0) sred[wid] = lsum;
    __syncthreads();
    if (t == 0) {
        float v = 0.f;
        #pragma unroll
        for (int w = 0; w < 8; w++) v += sred[w];
        sbcast = 1.f / v;
    }
    __syncthreads();
    float inv = sbcast;

    unsigned short hv[4];
    #pragma unroll
    for (int e = 0; e < 4; e++)
        hv[e] = __half_as_ushort(__float2half_rn(ex[e] * inv));
    uint2 hp = make_uint2((unsigned)hv[0] | ((unsigned)hv[1] << 16),
                          (unsigned)hv[2] | ((unsigned)hv[3] << 16));
    *(uint2*)&g_al[(size_t)bid * NN + 4 * t] = hp;
}

// ---------------- GEMM1: all 4 directions per CTA, in-register masking ----------------
// per (b, mtile, ntile): for d in 0..3: Z_d[64 i x 128 f] = sum_j (alpha*bit_d)[i,j] * xt[f,j]
// A = alpha (single fp16), B = xt (2-term split). 2 MMAs per (n-half, d).
// CTA 256 thr, 8 warps (4M x 2N): warp tile m16 x n64. acc[4][8][4].
// smem stage: A(64x80) | Bh(128x80) | Bl(128x80) | Mask(64x16B)
#define A1_BYTES  (64 * 80)                    // 5120
#define B1_BYTES  (128 * 80)                   // 10240
#define MK_OFF    (A1_BYTES + 2 * B1_BYTES)    // 25600
#define ST1_BYTES (MK_OFF + 64 * 16)           // 26624
#define GS1       (2 * ST1_BYTES)              // 53248

__global__ void __launch_bounds__(256, 1) gemm1(void) {
    extern __shared__ __align__(16) char smem[];
    uint32_t sbase = smem_u32(smem);

    int t = threadIdx.x, lane = t & 31, wid = t >> 5;
    int mtile = blockIdx.x, ntile = blockIdx.y, b = blockIdx.z;
    int i0 = mtile * 64;
    int n0 = ntile * 128;

    const __half* a_p = g_al + ((size_t)(b * NN) + i0) * NN;
    const __half* b_h = g_xt_h + (size_t)b * FIN * NN + (size_t)n0 * NN;
    const __half* b_l = g_xt_l + (size_t)b * FIN * NN + (size_t)n0 * NN;

    int ra = t >> 2, cha = t & 3;            // A rows 0..63, 4 chunks
    int rb1 = t >> 2, rb2 = 64 + (t >> 2);   // B rows, 4 chunks
    uint32_t soA = (uint32_t)(ra * 80 + cha * 16);
    uint32_t soB1 = (uint32_t)(rb1 * 80 + cha * 16);
    uint32_t soB2 = (uint32_t)(rb2 * 80 + cha * 16);

    int m_w = (wid >> 1) * 16;
    int n_w = (wid & 1) * 64;

    float acc[4][8][4] = {};

    auto issue = [&](int stage, int kc) {
        uint32_t st = sbase + stage * ST1_BYTES;
        size_t oa = (size_t)ra * NN + kc * 32 + cha * 8;
        CP16(st + soA, a_p + oa);
        size_t ob1 = (size_t)rb1 * NN + kc * 32 + cha * 8;
        size_t ob2 = (size_t)rb2 * NN + kc * 32 + cha * 8;
        CP16(st + A1_BYTES + soB1,            b_h + ob1);
        CP16(st + A1_BYTES + soB2,            b_h + ob2);
        CP16(st + A1_BYTES + B1_BYTES + soB1, b_l + ob1);
        CP16(st + A1_BYTES + B1_BYTES + soB2, b_l + ob2);
        if (t < 64)
            CP16(st + MK_OFF + t * 16, (const char*)&g_Abits[(size_t)(i0 + t) * 32 + kc]);
    };

    issue(0, 0);
    CP_COMMIT();
    issue(1, 1);
    CP_COMMIT();

    #pragma unroll 1
    for (int kc = 0; kc < 32; kc++) {
        int s = kc & 1;
        if (kc == 31) CP_WAIT0(); else CP_WAIT1();
        __syncthreads();

        uint32_t uA = sbase + s * ST1_BYTES;
        uint32_t uBh = uA + A1_BYTES;
        uint32_t uBl = uBh + B1_BYTES;
        const uint4* mk = (const uint4*)(smem + s * ST1_BYTES + MK_OFF);

        int rr = m_w + (lane >> 2);
        uint4 w0 = mk[rr];
        uint4 w1 = mk[rr + 8];

        #pragma unroll
        for (int s16 = 0; s16 < 2; s16++) {
            uint32_t ah[4];
            {
                uint32_t off = (uint32_t)((m_w + (lane & 15)) * 80 +
                                          s16 * 32 + (lane >> 4) * 16);
                LDSM_X4(ah[0], ah[1], ah[2], ah[3], uA + off);
            }
            uint32_t bh[4][4], bl[4][4];
            #pragma unroll
            for (int p = 0; p < 4; p++) {
                uint32_t off = (uint32_t)((n_w + p * 16 + (lane & 15)) * 80 +
                                          s16 * 32 + (lane >> 4) * 16);
                LDSM_X4(bh[p][0], bh[p][1], bh[p][2], bh[p][3], uBh + off);
                LDSM_X4(bl[p][0], bl[p][1], bl[p][2], bl[p][3], uBl + off);
            }
            int sh = s16 * 16 + (lane & 3) * 2;
            #pragma unroll
            for (int d = 0; d < 4; d++) {
                unsigned wd0 = (&w0.x)[d];
                unsigned wd1 = (&w1.x)[d];
                uint32_t m0 = expand2((wd0 >> sh) & 3u);
                uint32_t m1 = expand2((wd1 >> sh) & 3u);
                uint32_t m2 = expand2((wd0 >> (sh + 8)) & 3u);
                uint32_t m3 = expand2((wd1 >> (sh + 8)) & 3u);
                uint32_t amh[4] = {ah[0] & m0, ah[1] & m1, ah[2] & m2, ah[3] & m3};
                #pragma unroll
                for (int p = 0; p < 4; p++) {
                    mma16816(acc[d][2 * p],     amh, bh[p][0], bh[p][2]);
                    mma16816(acc[d][2 * p],     amh, bl[p][0], bl[p][2]);
                    mma16816(acc[d][2 * p + 1], amh, bh[p][1], bh[p][3]);
                    mma16816(acc[d][2 * p + 1], amh, bl[p][1], bl[p][3]);
                }
            }
        }
        __syncthreads();
        if (kc + 2 < 32) {
            issue(s, kc + 2);
            CP_COMMIT();
        }
    }

    // ---- epilogue: split-fp16 Z stores for all 4 d ----
    #pragma unroll
    for (int d = 0; d < 4; d++) {
        #pragma unroll
        for (int ni = 0; ni < 8; ni++) {
            int col = n_w + ni * 8 + (lane & 3) * 2;
            #pragma unroll
            for (int hh = 0; hh < 2; hh++) {
                int row = m_w + (lane >> 2) + hh * 8;
                float v0 = acc[d][ni][hh * 2 + 0];
                float v1 = acc[d][ni][hh * 2 + 1];
                __half h0, l0, h1, l1;
                split_h16(v0, h0, l0);
                split_h16(v1, h1, l1);
                unsigned hp = ((unsigned)__half_as_ushort(h1) << 16) | __half_as_ushort(h0);
                unsigned lp = ((unsigned)__half_as_ushort(l1) << 16) | __half_as_ushort(l0);
                size_t zoff = ((size_t)(b * NN) + i0 + row) * 1024 + d * 256 + n0 + col;
                *(unsigned*)&g_z_h[zoff] = hp;
                *(unsigned*)&g_z_l[zoff] = lp;
            }
        }
    }
}

// ---------------- GEMM2: out = 0.5 * (Zh+Zl) @ Wt^T, W single fp16 ----------------
#define KCHUNKS     32
#define ARR2_BYTES  (128 * 80)          // 10240
#define ST2_BYTES   (3 * ARR2_BYTES)    // 30720: Ah | Al | Bh
#define GS2         (2 * ST2_BYTES)     // 61440

__global__ void __launch_bounds__(256, 2) gemm2(float* __restrict__ out) {
    extern __shared__ __align__(16) char smem[];
    uint32_t sbase = smem_u32(smem);

    int t = threadIdx.x, lane = t & 31, wid = t >> 5;
    int mtile = blockIdx.x, ntile = blockIdx.y, b = blockIdx.z;
    int i0 = mtile * 128;
    int n0 = ntile * 128;

    const __half* a_h = g_z_h + ((size_t)(b * NN) + i0) * 1024;
    const __half* a_l = g_z_l + ((size_t)(b * NN) + i0) * 1024;
    const __half* b_h = g_wt + (size_t)n0 * 1024;

    int r1 = t >> 2,          ch1 = t & 3;
    int r2 = (t + 256) >> 2,  ch2 = (t + 256) & 3;
    uint32_t so1 = (uint32_t)(r1 * 80 + ch1 * 16);
    uint32_t so2 = (uint32_t)(r2 * 80 + ch2 * 16);

    int m_w = (wid >> 1) * 32;
    int n_w = (wid & 1) * 64;

    float acc[2][8][4] = {};

    auto issue = [&](int stage, int k0) {
        uint32_t st = sbase + stage * ST2_BYTES;
        size_t o1 = (size_t)r1 * 1024 + k0 + ch1 * 8;
        size_t o2 = (size_t)r2 * 1024 + k0 + ch2 * 8;
        CP16(st + so1,                  a_h + o1);
        CP16(st + so2,                  a_h + o2);
        CP16(st + ARR2_BYTES + so1,     a_l + o1);
        CP16(st + ARR2_BYTES + so2,     a_l + o2);
        CP16(st + 2 * ARR2_BYTES + so1, b_h + o1);
        CP16(st + 2 * ARR2_BYTES + so2, b_h + o2);
    };

    issue(0, 0);
    CP_COMMIT();
    issue(1, 32);
    CP_COMMIT();

    #pragma unroll 1
    for (int kc = 0; kc < KCHUNKS; kc++) {
        int s = kc & 1;
        if (kc == KCHUNKS - 1) CP_WAIT0(); else CP_WAIT1();
        __syncthreads();

        uint32_t uA_h = sbase + s * ST2_BYTES;
        uint32_t uA_l = uA_h + ARR2_BYTES;
        uint32_t uB_h = uA_h + 2 * ARR2_BYTES;

        #pragma unroll
        for (int s16 = 0; s16 < 2; s16++) {
            uint32_t ah[2][4], al[2][4];
            #pragma unroll
            for (int mi = 0; mi < 2; mi++) {
                uint32_t off = (uint32_t)((m_w + mi * 16 + (lane & 15)) * 80 +
                                          s16 * 32 + (lane >> 4) * 16);
                LDSM_X4(ah[mi][0], ah[mi][1], ah[mi][2], ah[mi][3], uA_h + off);
                LDSM_X4(al[mi][0], al[mi][1], al[mi][2], al[mi][3], uA_l + off);
            }
            #pragma unroll
            for (int p = 0; p < 4; p++) {
                uint32_t off = (uint32_t)((n_w + p * 16 + (lane & 15)) * 80 +
                                          s16 * 32 + (lane >> 4) * 16);
                uint32_t bh[4];
                LDSM_X4(bh[0], bh[1], bh[2], bh[3], uB_h + off);
                #pragma unroll
                for (int mi = 0; mi < 2; mi++) {
                    mma16816(acc[mi][2 * p],     ah[mi], bh[0], bh[2]);
                    mma16816(acc[mi][2 * p],     al[mi], bh[0], bh[2]);
                    mma16816(acc[mi][2 * p + 1], ah[mi], bh[1], bh[3]);
                    mma16816(acc[mi][2 * p + 1], al[mi], bh[1], bh[3]);
                }
            }
        }
        __syncthreads();
        if (kc + 2 < KCHUNKS) {
            issue(s, (kc + 2) * 32);
            CP_COMMIT();
        }
    }

    #pragma unroll
    for (int mi = 0; mi < 2; mi++) {
        #pragma unroll
        for (int ni = 0; ni < 8; ni++) {
            int col = n_w + ni * 8 + (lane & 3) * 2;
            #pragma unroll
            for (int hh = 0; hh < 2; hh++) {
                int row = m_w + mi * 16 + (lane >> 2) + hh * 8;
                size_t ooff = ((size_t)(b * NN) + i0 + row) * 256 + n0 + col;
                float2 v = make_float2(0.5f * acc[mi][ni][hh * 2 + 0],
                                       0.5f * acc[mi][ni][hh * 2 + 1]);
                *(float2*)&out[ooff] = v;
            }
        }
    }
}

// ---------------- launch ----------------
extern "C" void kernel_launch(void* const* d_in, const int* in_sizes, int n_in,
                              void* d_out, int out_size) {
    const float* x  = (const float*)d_in[0];
    const int*   AU = (const int*)d_in[1];
    const int*   AD = (const int*)d_in[2];
    const int*   AR = (const int*)d_in[3];
    const int*   AL = (const int*)d_in[4];
    const float* W  = (const float*)d_in[5];
    const float* a  = (const float*)d_in[6];
    float* out = (float*)d_out;

    cudaFuncSetAttribute(gemm1, cudaFuncAttributeMaxDynamicSharedMemorySize, GS1);
    cudaFuncSetAttribute(gemm2, cudaFuncAttributeMaxDynamicSharedMemorySize, GS2);

    prep_kernel<<<DD * FIN, 256>>>(W, a);
    apack_kernel<<<(NN * NN) / 256, 256>>>(AU, AD, AR, AL);
    abits_kernel<<<(NN * 32) / 256, 256>>>();
    xt_kernel<<<dim3(NN / 32, FIN / 32, BB), dim3(32, 8)>>>(x);
    edge_kernel<<<MTOT / 8, 256>>>(x);
    softmax_kernel<<<MTOT, 256>>>();
    gemm1<<<dim3(16, 2, BB), 256, GS1>>>();
    gemm2<<<dim3(8, 2, BB), 256, GS2>>>(out);
}

// round 13
// speedup vs baseline: 5.0734x; 1.5549x over previous
#include <cuda_runtime.h>
#include <cuda_fp16.h>
#include <math_constants.h>
#include <cstdint>

// Problem constants
#define BB   8
#define NN   1024
#define FIN  256
#define OUTD 256
#define DD   4
#define MTOT (BB * NN)   // 8192

// ---------------- scratch (static device globals; no dynamic alloc) ----------------
__device__ float g_wsrc[DD * FIN];
__device__ float g_wdst[DD * FIN];
__device__ float g_esrc[DD * MTOT];
__device__ float g_edst[DD * MTOT];
__device__ __align__(16) unsigned char g_Apack[NN * NN];              // 1 MB
__device__ __align__(16) uint4 g_Abits[NN * 32];                      // 0.5 MB bit-planes
__device__ __align__(16) __half g_al[(size_t)MTOT * NN];              // 16 MB alpha (fp16)
__device__ __align__(16) __half g_xt[BB * FIN * NN];                  // 4 MB  [b][f][j]
__device__ __align__(16) __half g_z[(size_t)MTOT * 1024];             // 16 MB [b][i][d*256+f]
__device__ __align__(16) __half g_wt[OUTD * 1024];                    // 0.5 MB [o][d*256+f]

// ---------------- helpers ----------------
__device__ __forceinline__ uint32_t smem_u32(const void* p) {
    uint32_t a;
    asm("{ .reg .u64 t; cvta.to.shared.u64 t, %1; cvt.u32.u64 %0, t; }" : "=r"(a) : "l"(p));
    return a;
}
__device__ __forceinline__ float warpSum(float v) {
    #pragma unroll
    for (int o = 16; o; o >>= 1) v += __shfl_xor_sync(0xffffffffu, v, o);
    return v;
}
// expand 2 adjacency bits -> per-half 0xFFFF masks
__device__ __forceinline__ uint32_t expand2(uint32_t b) {
    return (0xFFFFu & (0u - (b & 1u))) | (0xFFFF0000u & (0u - (b >> 1)));
}

#define LDSM_X4(r0, r1, r2, r3, addr)                                           \
    asm volatile("ldmatrix.sync.aligned.m8n8.x4.shared.b16 {%0,%1,%2,%3}, [%4];"\
                 : "=r"(r0), "=r"(r1), "=r"(r2), "=r"(r3) : "r"(addr))

#define CP16(dst, src)                                                          \
    asm volatile("cp.async.cg.shared.global [%0], [%1], 16;"                    \
                 :: "r"(dst), "l"(src))
#define CP_COMMIT() asm volatile("cp.async.commit_group;" ::: "memory")
#define CP_WAIT1()  asm volatile("cp.async.wait_group 1;" ::: "memory")
#define CP_WAIT0()  asm volatile("cp.async.wait_group 0;" ::: "memory")

__device__ __forceinline__ void mma16816(float c[4], const uint32_t a[4],
                                         uint32_t b0, uint32_t b1) {
    asm volatile(
        "mma.sync.aligned.m16n8k16.row.col.f32.f16.f16.f32 "
        "{%0,%1,%2,%3}, {%4,%5,%6,%7}, {%8,%9}, {%0,%1,%2,%3};"
        : "+f"(c[0]), "+f"(c[1]), "+f"(c[2]), "+f"(c[3])
        : "r"(a[0]), "r"(a[1]), "r"(a[2]), "r"(a[3]), "r"(b0), "r"(b1));
}

// ---------------- prep: w_src/w_dst (head 1) + Wt = transposed fp16 Wsum ----------------
__global__ void prep_kernel(const float* __restrict__ W, const float* __restrict__ a) {
    int d = blockIdx.x >> 8;
    int f = blockIdx.x & 255;
    int o = threadIdx.x;

    float w0 = W[((size_t)(d * 2 + 0) * FIN + f) * OUTD + o];
    float w1 = W[((size_t)(d * 2 + 1) * FIN + f) * OUTD + o];
    float wsum = w0 + w1;
    size_t wo = (size_t)o * 1024 + d * 256 + f;   // [o][d*256+f]
    g_wt[wo] = __float2half_rn(wsum);

    float a_s = a[(d * 2 + 1) * (2 * OUTD) + o];
    float a_d = a[(d * 2 + 1) * (2 * OUTD) + OUTD + o];
    float s1 = warpSum(w1 * a_s);
    float s2 = warpSum(w1 * a_d);
    __shared__ float r1[8], r2[8];
    int lane = threadIdx.x & 31, wid = threadIdx.x >> 5;
    if (lane == 0) { r1[wid] = s1; r2[wid] = s2; }
    __syncthreads();
    if (threadIdx.x == 0) {
        float t1 = 0.f, t2 = 0.f;
        #pragma unroll
        for (int w = 0; w < 8; w++) { t1 += r1[w]; t2 += r2[w]; }
        g_wsrc[d * FIN + f] = t1;
        g_wdst[d * FIN + f] = t2;
    }
}

// ---------------- pack adjacency bits ----------------
__global__ void apack_kernel(const int* __restrict__ AU, const int* __restrict__ AD,
                             const int* __restrict__ AR, const int* __restrict__ AL) {
    int idx = blockIdx.x * 256 + threadIdx.x;
    unsigned m = (AU[idx] != 0 ? 1u : 0u) | (AD[idx] != 0 ? 2u : 0u) |
                 (AR[idx] != 0 ? 4u : 0u) | (AL[idx] != 0 ? 8u : 0u);
    g_Apack[idx] = (unsigned char)m;
}

// ---------------- adjacency bit-planes: g_Abits[i*32+j32].d = 32 j-bits of dir d ----------------
__global__ void abits_kernel() {
    int idx = blockIdx.x * 256 + threadIdx.x;  // 32768 = 1024 * 32
    int i = idx >> 5, j32 = idx & 31;
    const unsigned* src = (const unsigned*)(g_Apack + (size_t)i * NN + j32 * 32);
    unsigned w[4] = {0, 0, 0, 0};
    #pragma unroll
    for (int q = 0; q < 8; q++) {
        unsigned v = src[q];
        #pragma unroll
        for (int e = 0; e < 4; e++) {
            unsigned nib = (v >> (8 * e)) & 0xFu;
            #pragma unroll
            for (int d = 0; d < 4; d++)
                w[d] |= ((nib >> d) & 1u) << (q * 4 + e);
        }
    }
    g_Abits[idx] = make_uint4(w[0], w[1], w[2], w[3]);
}

// ---------------- x transpose + fp16: Xt[b][f][j] ----------------
__global__ void xt_kernel(const float* __restrict__ x) {
    __shared__ float tile[32][33];
    int j0 = blockIdx.x * 32, f0 = blockIdx.y * 32, b = blockIdx.z;
    int tx = threadIdx.x, ty = threadIdx.y;
    #pragma unroll
    for (int r = 0; r < 4; r++)
        tile[ty + 8 * r][tx] = x[((size_t)(b * NN) + j0 + ty + 8 * r) * FIN + f0 + tx];
    __syncthreads();
    #pragma unroll
    for (int r = 0; r < 4; r++) {
        int f = f0 + ty + 8 * r;
        int j = j0 + tx;
        float v = tile[tx][ty + 8 * r];
        g_xt[((size_t)(b * FIN) + f) * NN + j] = __float2half_rn(v);
    }
}

// ---------------- e_src/e_dst: one warp per m, all 4 directions ----------------
__global__ void edge_kernel(const float* __restrict__ x) {
    int wid = threadIdx.x >> 5, lane = threadIdx.x & 31;
    int m = blockIdx.x * 8 + wid;
    const float* xr = x + (size_t)m * FIN;
    float xv[8];
    #pragma unroll
    for (int it = 0; it < 8; it++) xv[it] = xr[lane + 32 * it];
    #pragma unroll
    for (int d = 0; d < DD; d++) {
        float s1 = 0.f, s2 = 0.f;
        #pragma unroll
        for (int it = 0; it < 8; it++) {
            int k = lane + 32 * it;
            s1 += xv[it] * g_wsrc[d * FIN + k];
            s2 += xv[it] * g_wdst[d * FIN + k];
        }
        s1 = warpSum(s1);
        s2 = warpSum(s2);
        if (lane == 0) { g_esrc[d * MTOT + m] = s1; g_edst[d * MTOT + m] = s2; }
    }
}

// ---------------- softmax over j; emits single fp16 alpha ----------------
__global__ void softmax_kernel() {
    int bid = blockIdx.x;
    int b = bid >> 10;
    int i = bid & 1023;
    int t = threadIdx.x;
    int lane = t & 31, wid = t >> 5;

    __shared__ float s_esrc[4];
    __shared__ float sred[8];
    __shared__ float sbcast;

    if (t < 4) s_esrc[t] = g_esrc[t * MTOT + bid];
    __syncthreads();

    unsigned mword = *(const unsigned*)(g_Apack + (size_t)i * NN + 4 * t);

    const float NEGINF = -CUDART_INF_F;
    float ev[4];
    float lmax = NEGINF;
    #pragma unroll
    for (int e = 0; e < 4; e++) {
        unsigned m = (mword >> (8 * e)) & 0xFu;
        float val = NEGINF;
        if (m) {
            int ds = 31 - __clz(m);
            float v = s_esrc[ds] + g_edst[ds * MTOT + b * NN + 4 * t + e];
            val = v > 0.f ? v : 0.01f * v;
        }
        ev[e] = val;
        lmax = fmaxf(lmax, val);
    }
    #pragma unroll
    for (int o = 16; o; o >>= 1) lmax = fmaxf(lmax, __shfl_xor_sync(0xffffffffu, lmax, o));
    if (lane == 0) sred[wid] = lmax;
    __syncthreads();
    if (t == 0) {
        float v = sred[0];
        #pragma unroll
        for (int w = 1; w < 8; w++) v = fmaxf(v, sred[w]);
        sbcast = v;
    }
    __syncthreads();
    float rmax = sbcast;
    __syncthreads();

    float ex[4];
    float lsum = 0.f;
    #pragma unroll
    for (int e = 0; e < 4; e++) {
        float val = ev[e];
        float xx = (val == NEGINF) ? 0.f : __expf(val - rmax);
        ex[e] = xx;
        lsum += xx;
    }
    lsum = warpSum(lsum);
    if (lane == 0) sred[wid] = lsum;
    __syncthreads();
    if (t == 0) {
        float v = 0.f;
        #pragma unroll
        for (int w = 0; w < 8; w++) v += sred[w];
        sbcast = 1.f / v;
    }
    __syncthreads();
    float inv = sbcast;

    unsigned short hv[4];
    #pragma unroll
    for (int e = 0; e < 4; e++)
        hv[e] = __half_as_ushort(__float2half_rn(ex[e] * inv));
    uint2 hp = make_uint2((unsigned)hv[0] | ((unsigned)hv[1] << 16),
                          (unsigned)hv[2] | ((unsigned)hv[3] << 16));
    *(uint2*)&g_al[(size_t)bid * NN + 4 * t] = hp;
}

// ---------------- GEMM1: all 4 directions per CTA, in-register masking, pure fp16 ----------------
// per (b, mtile, ntile): for d in 0..3: Z_d[64 i x 128 f] = sum_j (alpha*bit_d)[i,j] * xt[f,j]
// CTA 256 thr, 8 warps (4M x 2N): warp tile m16 x n64. acc[4][8][4].
// smem stage: A(64x80) | B(128x80) | Mask(64x16B) = 16384 B
#define A1_BYTES  (64 * 80)                 // 5120
#define B1_BYTES  (128 * 80)                // 10240
#define MK_OFF    (A1_BYTES + B1_BYTES)     // 15360
#define ST1_BYTES (MK_OFF + 64 * 16)        // 16384
#define GS1       (2 * ST1_BYTES)           // 32768

__global__ void __launch_bounds__(256, 1) gemm1(void) {
    extern __shared__ __align__(16) char smem[];
    uint32_t sbase = smem_u32(smem);

    int t = threadIdx.x, lane = t & 31, wid = t >> 5;
    int mtile = blockIdx.x, ntile = blockIdx.y, b = blockIdx.z;
    int i0 = mtile * 64;
    int n0 = ntile * 128;

    const __half* a_p = g_al + ((size_t)(b * NN) + i0) * NN;
    const __half* b_p = g_xt + (size_t)b * FIN * NN + (size_t)n0 * NN;

    int ra = t >> 2, cha = t & 3;            // A rows 0..63, 4 chunks
    int rb1 = t >> 2, rb2 = 64 + (t >> 2);   // B rows, 4 chunks
    uint32_t soA = (uint32_t)(ra * 80 + cha * 16);
    uint32_t soB1 = (uint32_t)(rb1 * 80 + cha * 16);
    uint32_t soB2 = (uint32_t)(rb2 * 80 + cha * 16);

    int m_w = (wid >> 1) * 16;
    int n_w = (wid & 1) * 64;

    float acc[4][8][4] = {};

    auto issue = [&](int stage, int kc) {
        uint32_t st = sbase + stage * ST1_BYTES;
        size_t oa = (size_t)ra * NN + kc * 32 + cha * 8;
        CP16(st + soA, a_p + oa);
        size_t ob1 = (size_t)rb1 * NN + kc * 32 + cha * 8;
        size_t ob2 = (size_t)rb2 * NN + kc * 32 + cha * 8;
        CP16(st + A1_BYTES + soB1, b_p + ob1);
        CP16(st + A1_BYTES + soB2, b_p + ob2);
        if (t < 64)
            CP16(st + MK_OFF + t * 16, (const char*)&g_Abits[(size_t)(i0 + t) * 32 + kc]);
    };

    issue(0, 0);
    CP_COMMIT();
    issue(1, 1);
    CP_COMMIT();

    #pragma unroll 1
    for (int kc = 0; kc < 32; kc++) {
        int s = kc & 1;
        if (kc == 31) CP_WAIT0(); else CP_WAIT1();
        __syncthreads();

        uint32_t uA = sbase + s * ST1_BYTES;
        uint32_t uB = uA + A1_BYTES;
        const uint4* mk = (const uint4*)(smem + s * ST1_BYTES + MK_OFF);

        int rr = m_w + (lane >> 2);
        uint4 w0 = mk[rr];
        uint4 w1 = mk[rr + 8];

        #pragma unroll
        for (int s16 = 0; s16 < 2; s16++) {
            uint32_t ah[4];
            {
                uint32_t off = (uint32_t)((m_w + (lane & 15)) * 80 +
                                          s16 * 32 + (lane >> 4) * 16);
                LDSM_X4(ah[0], ah[1], ah[2], ah[3], uA + off);
            }
            uint32_t bh[4][4];
            #pragma unroll
            for (int p = 0; p < 4; p++) {
                uint32_t off = (uint32_t)((n_w + p * 16 + (lane & 15)) * 80 +
                                          s16 * 32 + (lane >> 4) * 16);
                LDSM_X4(bh[p][0], bh[p][1], bh[p][2], bh[p][3], uB + off);
            }
            int sh = s16 * 16 + (lane & 3) * 2;
            #pragma unroll
            for (int d = 0; d < 4; d++) {
                unsigned wd0 = (&w0.x)[d];
                unsigned wd1 = (&w1.x)[d];
                uint32_t m0 = expand2((wd0 >> sh) & 3u);
                uint32_t m1 = expand2((wd1 >> sh) & 3u);
                uint32_t m2 = expand2((wd0 >> (sh + 8)) & 3u);
                uint32_t m3 = expand2((wd1 >> (sh + 8)) & 3u);
                uint32_t amh[4] = {ah[0] & m0, ah[1] & m1, ah[2] & m2, ah[3] & m3};
                #pragma unroll
                for (int p = 0; p < 4; p++) {
                    mma16816(acc[d][2 * p],     amh, bh[p][0], bh[p][2]);
                    mma16816(acc[d][2 * p + 1], amh, bh[p][1], bh[p][3]);
                }
            }
        }
        __syncthreads();
        if (kc + 2 < 32) {
            issue(s, kc + 2);
            CP_COMMIT();
        }
    }

    // ---- epilogue: fp16 Z stores for all 4 d ----
    #pragma unroll
    for (int d = 0; d < 4; d++) {
        #pragma unroll
        for (int ni = 0; ni < 8; ni++) {
            int col = n_w + ni * 8 + (lane & 3) * 2;
            #pragma unroll
            for (int hh = 0; hh < 2; hh++) {
                int row = m_w + (lane >> 2) + hh * 8;
                unsigned short h0 = __half_as_ushort(__float2half_rn(acc[d][ni][hh * 2 + 0]));
                unsigned short h1 = __half_as_ushort(__float2half_rn(acc[d][ni][hh * 2 + 1]));
                unsigned hp = ((unsigned)h1 << 16) | h0;
                size_t zoff = ((size_t)(b * NN) + i0 + row) * 1024 + d * 256 + n0 + col;
                *(unsigned*)&g_z[zoff] = hp;
            }
        }
    }
}

// ---------------- GEMM2: out = 0.5 * Z @ Wt^T, pure fp16 ----------------
#define KCHUNKS     32
#define ARR2_BYTES  (128 * 80)          // 10240
#define ST2_BYTES   (2 * ARR2_BYTES)    // 20480: A | B
#define GS2         (2 * ST2_BYTES)     // 40960

__global__ void __launch_bounds__(256, 2) gemm2(float* __restrict__ out) {
    extern __shared__ __align__(16) char smem[];
    uint32_t sbase = smem_u32(smem);

    int t = threadIdx.x, lane = t & 31, wid = t >> 5;
    int mtile = blockIdx.x, ntile = blockIdx.y, b = blockIdx.z;
    int i0 = mtile * 128;
    int n0 = ntile * 128;

    const __half* a_p = g_z + ((size_t)(b * NN) + i0) * 1024;
    const __half* b_p = g_wt + (size_t)n0 * 1024;

    int r1 = t >> 2,          ch1 = t & 3;
    int r2 = (t + 256) >> 2,  ch2 = (t + 256) & 3;
    uint32_t so1 = (uint32_t)(r1 * 80 + ch1 * 16);
    uint32_t so2 = (uint32_t)(r2 * 80 + ch2 * 16);

    int m_w = (wid >> 1) * 32;
    int n_w = (wid & 1) * 64;

    float acc[2][8][4] = {};

    auto issue = [&](int stage, int k0) {
        uint32_t st = sbase + stage * ST2_BYTES;
        size_t o1 = (size_t)r1 * 1024 + k0 + ch1 * 8;
        size_t o2 = (size_t)r2 * 1024 + k0 + ch2 * 8;
        CP16(st + so1,              a_p + o1);
        CP16(st + so2,              a_p + o2);
        CP16(st + ARR2_BYTES + so1, b_p + o1);
        CP16(st + ARR2_BYTES + so2, b_p + o2);
    };

    issue(0, 0);
    CP_COMMIT();
    issue(1, 32);
    CP_COMMIT();

    #pragma unroll 1
    for (int kc = 0; kc < KCHUNKS; kc++) {
        int s = kc & 1;
        if (kc == KCHUNKS - 1) CP_WAIT0(); else CP_WAIT1();
        __syncthreads();

        uint32_t uA = sbase + s * ST2_BYTES;
        uint32_t uB = uA + ARR2_BYTES;

        #pragma unroll
        for (int s16 = 0; s16 < 2; s16++) {
            uint32_t ah[2][4];
            #pragma unroll
            for (int mi = 0; mi < 2; mi++) {
                uint32_t off = (uint32_t)((m_w + mi * 16 + (lane & 15)) * 80 +
                                          s16 * 32 + (lane >> 4) * 16);
                LDSM_X4(ah[mi][0], ah[mi][1], ah[mi][2], ah[mi][3], uA + off);
            }
            #pragma unroll
            for (int p = 0; p < 4; p++) {
                uint32_t off = (uint32_t)((n_w + p * 16 + (lane & 15)) * 80 +
                                          s16 * 32 + (lane >> 4) * 16);
                uint32_t bh[4];
                LDSM_X4(bh[0], bh[1], bh[2], bh[3], uB + off);
                #pragma unroll
                for (int mi = 0; mi < 2; mi++) {
                    mma16816(acc[mi][2 * p],     ah[mi], bh[0], bh[2]);
                    mma16816(acc[mi][2 * p + 1], ah[mi], bh[1], bh[3]);
                }
            }
        }
        __syncthreads();
        if (kc + 2 < KCHUNKS) {
            issue(s, (kc + 2) * 32);
            CP_COMMIT();
        }
    }

    #pragma unroll
    for (int mi = 0; mi < 2; mi++) {
        #pragma unroll
        for (int ni = 0; ni < 8; ni++) {
            int col = n_w + ni * 8 + (lane & 3) * 2;
            #pragma unroll
            for (int hh = 0; hh < 2; hh++) {
                int row = m_w + mi * 16 + (lane >> 2) + hh * 8;
                size_t ooff = ((size_t)(b * NN) + i0 + row) * 256 + n0 + col;
                float2 v = make_float2(0.5f * acc[mi][ni][hh * 2 + 0],
                                       0.5f * acc[mi][ni][hh * 2 + 1]);
                *(float2*)&out[ooff] = v;
            }
        }
    }
}

// ---------------- launch ----------------
extern "C" void kernel_launch(void* const* d_in, const int* in_sizes, int n_in,
                              void* d_out, int out_size) {
    const float* x  = (const float*)d_in[0];
    const int*   AU = (const int*)d_in[1];
    const int*   AD = (const int*)d_in[2];
    const int*   AR = (const int*)d_in[3];
    const int*   AL = (const int*)d_in[4];
    const float* W  = (const float*)d_in[5];
    const float* a  = (const float*)d_in[6];
    float* out = (float*)d_out;

    cudaFuncSetAttribute(gemm1, cudaFuncAttributeMaxDynamicSharedMemorySize, GS1);
    cudaFuncSetAttribute(gemm2, cudaFuncAttributeMaxDynamicSharedMemorySize, GS2);

    prep_kernel<<<DD * FIN, 256>>>(W, a);
    apack_kernel<<<(NN * NN) / 256, 256>>>(AU, AD, AR, AL);
    abits_kernel<<<(NN * 32) / 256, 256>>>();
    xt_kernel<<<dim3(NN / 32, FIN / 32, BB), dim3(32, 8)>>>(x);
    edge_kernel<<<MTOT / 8, 256>>>(x);
    softmax_kernel<<<MTOT, 256>>>();
    gemm1<<<dim3(16, 2, BB), 256, GS1>>>();
    gemm2<<<dim3(8, 2, BB), 256, GS2>>>(out);
}